// round 10
// baseline (speedup 1.0000x reference)
#include <cuda_runtime.h>
#include <cstdint>
#include <math.h>

// ---------------- problem constants ----------------
#define BB   1024
#define IMG  512
#define TXT  300
#define NN   14
#define FF   2048
#define HID  128
#define CC   14
#define EE   182
#define DD   812     // IMG + TXT
#define D3   2436    // 3*D
#define MM   (BB*NN) // 14336 rows

// ---------------- scratch (device globals; no allocation) ----------------
__device__ float g_qkvi[(size_t)BB * D3];
__device__ float g_qkvt[(size_t)NN * D3];
__device__ float g_S0  [(size_t)BB * BB];
__device__ float g_Bq  [(size_t)NN * BB];
__device__ float g_Vo  [(size_t)BB * DD];
__device__ float g_ovt [(size_t)NN * DD];
__device__ float g_attn[(size_t)NN * BB * BB];
__device__ float g_ao2 [(size_t)MM * DD];
__device__ float g_x1  [(size_t)MM * DD];
__device__ float g_x1r [(size_t)MM * DD];
__device__ float g_hid [(size_t)MM * FF];
__device__ float g_ff  [(size_t)MM * DD];
__device__ float g_x2  [(size_t)MM * DD];
__device__ float g_g1  [(size_t)MM * HID];
__device__ float g_g2  [(size_t)MM * HID];
__device__ float g_g3  [(size_t)MM * HID];
__device__ float g_g4  [(size_t)MM * HID];
__device__ float g_pool[(size_t)BB * HID];

// rounded copies
__device__ float g_imgr [(size_t)BB * IMG];
__device__ float g_inwr [(size_t)D3 * DD];
__device__ float g_outwr[(size_t)DD * DD];
__device__ float g_w1r  [(size_t)DD * FF];
__device__ float g_w2r  [(size_t)FF * DD];
__device__ float g_gw1r [(size_t)DD * HID];
__device__ float g_gw2r [(size_t)HID * HID];

__device__ int   g_eoff[NN + 1];
__device__ int   g_esrc[EE + NN + 16];
__device__ float g_ewt [EE + NN + 16];

__device__ __forceinline__ float tf32r(float f) {
    uint32_t r;
    asm("cvt.rna.tf32.f32 %0, %1;" : "=r"(r) : "f"(f));
    return __uint_as_float(r);
}

// ---------------- fused multi-segment round-copy ----------------
struct RCSeg { const float* src; float* dst; long long n4; };
struct RCTab { RCSeg s[7]; };

__global__ void round_copy_multi(RCTab tab) {
    long long i = (long long)blockIdx.x * blockDim.x + threadIdx.x;
#pragma unroll
    for (int k = 0; k < 7; k++) {
        if (i < tab.s[k].n4) {
            float4 v = *(const float4*)(tab.s[k].src + i * 4);
            v.x = tf32r(v.x); v.y = tf32r(v.y);
            v.z = tf32r(v.z); v.w = tf32r(v.w);
            *(float4*)(tab.s[k].dst + i * 4) = v;
            return;
        }
        i -= tab.s[k].n4;
    }
}

// ====== common MMA helper ======
__device__ __forceinline__ void mma_tf32(float c[4], const uint32_t a[4],
                                         const uint32_t b[2]) {
    asm volatile(
        "mma.sync.aligned.m16n8k8.row.col.f32.tf32.tf32.f32 "
        "{%0,%1,%2,%3}, {%4,%5,%6,%7}, {%8,%9}, {%0,%1,%2,%3};"
        : "+f"(c[0]), "+f"(c[1]), "+f"(c[2]), "+f"(c[3])
        : "r"(a[0]), "r"(a[1]), "r"(a[2]), "r"(a[3]), "r"(b[0]), "r"(b[1]));
}

// ================= tg256: 64x128 tile, 256 threads, 4-stage =================
// (for grid-limited GEMMs; identical math to R7/R9 IM=1)
#define C4_STAGES 4
#define C4_A_U32 1280
#define C4_STAGE_U32 3840
#define C4_SMEM (C4_STAGES * C4_STAGE_U32 * 4)

template <bool BT>
__device__ __forceinline__ void ca_fetch256(
    int k0, int M, int N, int K,
    const float* __restrict__ A, long long lda,
    const float* __restrict__ B, long long ldb,
    int m0, int n0, int tid, uint32_t sA_addr, uint32_t sB_addr) {
    {
        int arow = tid >> 2, acol = (tid & 3) * 4;
        int gm = m0 + arow;
        bool mv = gm < M;
        const float* rowp = A + (long long)(mv ? gm : m0) * lda;
        int gk = k0 + acol;
        int rem = K - gk;
        int vb = mv ? (rem >= 4 ? 16 : (rem > 0 ? rem * 4 : 0)) : 0;
        const float* src = rowp + (gk < K ? gk : 0);
        uint32_t dst = sA_addr + (uint32_t)(arow * 20 + acol) * 4u;
        asm volatile("cp.async.cg.shared.global [%0], [%1], 16, %2;"
                     :: "r"(dst), "l"(src), "r"(vb));
    }
    if (BT) {
        int arow = tid >> 1, acol = (tid & 1) * 8;
        int gj = n0 + arow;
        bool nv = gj < N;
        const float* rowp = B + (long long)(nv ? gj : n0) * ldb;
#pragma unroll
        for (int h = 0; h < 2; h++) {
            int gk = k0 + acol + h * 4;
            int rem = K - gk;
            int vb = nv ? (rem >= 4 ? 16 : (rem > 0 ? rem * 4 : 0)) : 0;
            const float* src = rowp + (gk < K ? gk : 0);
            uint32_t dst = sB_addr + (uint32_t)(arow * 20 + acol + h * 4) * 4u;
            asm volatile("cp.async.cg.shared.global [%0], [%1], 16, %2;"
                         :: "r"(dst), "l"(src), "r"(vb));
        }
    } else {
        int bkrow = tid >> 4, bncol = (tid & 15) * 8;
        int gk = k0 + bkrow;
        bool kv = gk < K;
        const float* rowp = B + (long long)(kv ? gk : k0) * ldb;
#pragma unroll
        for (int h = 0; h < 2; h++) {
            int gj = n0 + bncol + h * 4;
            int rem = N - gj;
            int vb = kv ? (rem >= 4 ? 16 : (rem > 0 ? rem * 4 : 0)) : 0;
            const float* src = rowp + (gj < N ? gj : 0);
            uint32_t dst = sB_addr + (uint32_t)(bkrow * 136 + bncol + h * 4) * 4u;
            asm volatile("cp.async.cg.shared.global [%0], [%1], 16, %2;"
                         :: "r"(dst), "l"(src), "r"(vb));
        }
    }
}

template <bool BT>
__global__ __launch_bounds__(256, 2)
void tg256(int M, int N, int K,
           const float* __restrict__ A, long long lda, long long sA,
           const float* __restrict__ B, long long ldb, long long sB,
           float* __restrict__ C, long long ldc, long long sC,
           const float* __restrict__ bias, long long sBias,
           float alpha, int relu, int round_out) {
    extern __shared__ uint32_t dsm[];

    int z = blockIdx.z;
    A += (long long)z * sA;
    B += (long long)z * sB;
    C += (long long)z * sC;
    if (bias) bias += (long long)z * sBias;

    int m0 = blockIdx.y * 64;
    int n0 = blockIdx.x * 128;
    int tid = threadIdx.x;
    int warp = tid >> 5, lane = tid & 31;
    int wm = warp >> 1, wn = warp & 1;
    int gid = lane >> 2, tig = lane & 3;

    uint32_t smem_base = (uint32_t)__cvta_generic_to_shared(dsm);

    float c[8][4];
#pragma unroll
    for (int j = 0; j < 8; j++)
#pragma unroll
        for (int r = 0; r < 4; r++) c[j][r] = 0.f;

    int ntiles = (K + 15) >> 4;

#pragma unroll
    for (int t = 0; t < C4_STAGES - 1; t++) {
        if (t < ntiles) {
            uint32_t sa = smem_base + (uint32_t)(t * C4_STAGE_U32) * 4u;
            ca_fetch256<BT>(t * 16, M, N, K, A, lda, B, ldb, m0, n0, tid,
                            sa, sa + (uint32_t)C4_A_U32 * 4u);
        }
        asm volatile("cp.async.commit_group;");
    }

    for (int t = 0; t < ntiles; t++) {
        asm volatile("cp.async.wait_group %0;" :: "n"(C4_STAGES - 2));
        __syncthreads();

        int nf = t + C4_STAGES - 1;
        if (nf < ntiles) {
            uint32_t sa = smem_base +
                (uint32_t)((nf % C4_STAGES) * C4_STAGE_U32) * 4u;
            ca_fetch256<BT>(nf * 16, M, N, K, A, lda, B, ldb, m0, n0, tid,
                            sa, sa + (uint32_t)C4_A_U32 * 4u);
        }
        asm volatile("cp.async.commit_group;");

        const uint32_t* sAu = dsm + (t % C4_STAGES) * C4_STAGE_U32;
        const uint32_t* sBu = sAu + C4_A_U32;

#pragma unroll
        for (int ks = 0; ks < 16; ks += 8) {
            uint32_t a[4], b[8][2];
            {
                int mb = wm * 16 + gid;
                a[0] = sAu[mb * 20 + ks + tig];
                a[1] = sAu[(mb + 8) * 20 + ks + tig];
                a[2] = sAu[mb * 20 + ks + tig + 4];
                a[3] = sAu[(mb + 8) * 20 + ks + tig + 4];
            }
#pragma unroll
            for (int j = 0; j < 8; j++) {
                int nb = wn * 64 + j * 8 + gid;
                if (BT) {
                    b[j][0] = sBu[nb * 20 + ks + tig];
                    b[j][1] = sBu[nb * 20 + ks + tig + 4];
                } else {
                    b[j][0] = sBu[(ks + tig) * 136 + nb];
                    b[j][1] = sBu[(ks + tig + 4) * 136 + nb];
                }
            }
#pragma unroll
            for (int j = 0; j < 8; j++) mma_tf32(c[j], a, b[j]);
        }
    }

    {
        int r0 = m0 + wm * 16 + gid;
#pragma unroll
        for (int j = 0; j < 8; j++) {
            int c0 = n0 + wn * 64 + j * 8 + 2 * tig;
#pragma unroll
            for (int rr = 0; rr < 2; rr++) {
                int gm = r0 + rr * 8;
                if (gm >= M) continue;
#pragma unroll
                for (int cc = 0; cc < 2; cc++) {
                    int gn = c0 + cc;
                    if (gn >= N) continue;
                    float v = c[j][rr * 2 + cc] * alpha;
                    if (bias) v += bias[gn];
                    if (relu) v = fmaxf(v, 0.f);
                    if (round_out) v = tf32r(v);
                    C[(long long)gm * ldc + gn] = v;
                }
            }
        }
    }
}

// ========== tg512: 128x128 tile, 512 threads (16 warps 8x2), 4-stage ========
#define C5_STAGES 4
#define C5_A_U32 2560            // 128 * 20
#define C5_STAGE_U32 5120        // A + B(2560)
#define C5_SMEM (C5_STAGES * C5_STAGE_U32 * 4)

template <bool BT>
__device__ __forceinline__ void ca_fetch512(
    int k0, int M, int N, int K,
    const float* __restrict__ A, long long lda,
    const float* __restrict__ B, long long ldb,
    int m0, int n0, int tid, uint32_t sA_addr, uint32_t sB_addr) {
    {
        int arow = tid >> 2, acol = (tid & 3) * 4;   // 128 rows x 16 k
        int gm = m0 + arow;
        bool mv = gm < M;
        const float* rowp = A + (long long)(mv ? gm : m0) * lda;
        int gk = k0 + acol;
        int rem = K - gk;
        int vb = mv ? (rem >= 4 ? 16 : (rem > 0 ? rem * 4 : 0)) : 0;
        const float* src = rowp + (gk < K ? gk : 0);
        uint32_t dst = sA_addr + (uint32_t)(arow * 20 + acol) * 4u;
        asm volatile("cp.async.cg.shared.global [%0], [%1], 16, %2;"
                     :: "r"(dst), "l"(src), "r"(vb));
    }
    if (BT) {
        int brow = tid >> 2, bcol = (tid & 3) * 4;   // 128 n-rows x 16 k
        int gj = n0 + brow;
        bool nv = gj < N;
        const float* rowp = B + (long long)(nv ? gj : n0) * ldb;
        int gk = k0 + bcol;
        int rem = K - gk;
        int vb = nv ? (rem >= 4 ? 16 : (rem > 0 ? rem * 4 : 0)) : 0;
        const float* src = rowp + (gk < K ? gk : 0);
        uint32_t dst = sB_addr + (uint32_t)(brow * 20 + bcol) * 4u;
        asm volatile("cp.async.cg.shared.global [%0], [%1], 16, %2;"
                     :: "r"(dst), "l"(src), "r"(vb));
    } else {
        int bkrow = tid >> 5, bncol = (tid & 31) * 4;  // 16 k-rows x 128 n
        int gk = k0 + bkrow;
        bool kv = gk < K;
        const float* rowp = B + (long long)(kv ? gk : k0) * ldb;
        int gj = n0 + bncol;
        int rem = N - gj;
        int vb = kv ? (rem >= 4 ? 16 : (rem > 0 ? rem * 4 : 0)) : 0;
        const float* src = rowp + (gj < N ? gj : 0);
        uint32_t dst = sB_addr + (uint32_t)(bkrow * 136 + bncol) * 4u;
        asm volatile("cp.async.cg.shared.global [%0], [%1], 16, %2;"
                     :: "r"(dst), "l"(src), "r"(vb));
    }
}

template <bool BT>
__global__ __launch_bounds__(512, 1)
void tg512(int M, int N, int K,
           const float* __restrict__ A, long long lda, long long sA,
           const float* __restrict__ B, long long ldb, long long sB,
           float* __restrict__ C, long long ldc, long long sC,
           const float* __restrict__ bias, long long sBias,
           float alpha, int relu, int round_out) {
    extern __shared__ uint32_t dsm[];

    int z = blockIdx.z;
    A += (long long)z * sA;
    B += (long long)z * sB;
    C += (long long)z * sC;
    if (bias) bias += (long long)z * sBias;

    int m0 = blockIdx.y * 128;
    int n0 = blockIdx.x * 128;
    int tid = threadIdx.x;
    int warp = tid >> 5, lane = tid & 31;
    int wm = warp >> 1, wn = warp & 1;        // 8 x 2, warp tile 16x64
    int gid = lane >> 2, tig = lane & 3;

    uint32_t smem_base = (uint32_t)__cvta_generic_to_shared(dsm);

    float c[8][4];
#pragma unroll
    for (int j = 0; j < 8; j++)
#pragma unroll
        for (int r = 0; r < 4; r++) c[j][r] = 0.f;

    int ntiles = (K + 15) >> 4;

#pragma unroll
    for (int t = 0; t < C5_STAGES - 1; t++) {
        if (t < ntiles) {
            uint32_t sa = smem_base + (uint32_t)(t * C5_STAGE_U32) * 4u;
            ca_fetch512<BT>(t * 16, M, N, K, A, lda, B, ldb, m0, n0, tid,
                            sa, sa + (uint32_t)C5_A_U32 * 4u);
        }
        asm volatile("cp.async.commit_group;");
    }

    for (int t = 0; t < ntiles; t++) {
        asm volatile("cp.async.wait_group %0;" :: "n"(C5_STAGES - 2));
        __syncthreads();

        int nf = t + C5_STAGES - 1;
        if (nf < ntiles) {
            uint32_t sa = smem_base +
                (uint32_t)((nf % C5_STAGES) * C5_STAGE_U32) * 4u;
            ca_fetch512<BT>(nf * 16, M, N, K, A, lda, B, ldb, m0, n0, tid,
                            sa, sa + (uint32_t)C5_A_U32 * 4u);
        }
        asm volatile("cp.async.commit_group;");

        const uint32_t* sAu = dsm + (t % C5_STAGES) * C5_STAGE_U32;
        const uint32_t* sBu = sAu + C5_A_U32;

#pragma unroll
        for (int ks = 0; ks < 16; ks += 8) {
            uint32_t a[4], b[8][2];
            {
                int mb = wm * 16 + gid;
                a[0] = sAu[mb * 20 + ks + tig];
                a[1] = sAu[(mb + 8) * 20 + ks + tig];
                a[2] = sAu[mb * 20 + ks + tig + 4];
                a[3] = sAu[(mb + 8) * 20 + ks + tig + 4];
            }
#pragma unroll
            for (int j = 0; j < 8; j++) {
                int nb = wn * 64 + j * 8 + gid;
                if (BT) {
                    b[j][0] = sBu[nb * 20 + ks + tig];
                    b[j][1] = sBu[nb * 20 + ks + tig + 4];
                } else {
                    b[j][0] = sBu[(ks + tig) * 136 + nb];
                    b[j][1] = sBu[(ks + tig + 4) * 136 + nb];
                }
            }
#pragma unroll
            for (int j = 0; j < 8; j++) mma_tf32(c[j], a, b[j]);
        }
    }

    {
        int r0 = m0 + wm * 16 + gid;
#pragma unroll
        for (int j = 0; j < 8; j++) {
            int c0 = n0 + wn * 64 + j * 8 + 2 * tig;
#pragma unroll
            for (int rr = 0; rr < 2; rr++) {
                int gm = r0 + rr * 8;
                if (gm >= M) continue;
#pragma unroll
                for (int cc = 0; cc < 2; cc++) {
                    int gn = c0 + cc;
                    if (gn >= N) continue;
                    float v = c[j][rr * 2 + cc] * alpha;
                    if (bias) v += bias[gn];
                    if (relu) v = fmaxf(v, 0.f);
                    if (round_out) v = tf32r(v);
                    C[(long long)gm * ldc + gn] = v;
                }
            }
        }
    }
}

// ================= thin GEMM for M == 14 =================
__global__ __launch_bounds__(256)
void thin_gemm_bt(int N, int K,
                  const float* __restrict__ A, long long lda,
                  const float* __restrict__ B, long long ldb,
                  float* __restrict__ C, long long ldc,
                  const float* __restrict__ bias) {
    __shared__ float sAm[NN][816];
    int tid = threadIdx.x;
    int K4 = K >> 2;
    for (int idx = tid; idx < NN * K4; idx += 256) {
        int m = idx / K4, k4 = idx - m * K4;
        *(float4*)&sAm[m][k4 * 4] = *(const float4*)(A + (long long)m * lda + k4 * 4);
    }
    __syncthreads();

    int n = blockIdx.x * 8 + (tid >> 5);
    int lane = tid & 31;
    float acc[NN];
#pragma unroll
    for (int m = 0; m < NN; m++) acc[m] = 0.f;

    if (n < N) {
        const float* Bp = B + (long long)n * ldb;
        for (int k = lane * 4; k + 4 <= K; k += 128) {
            float4 bv = *(const float4*)(Bp + k);
#pragma unroll
            for (int m = 0; m < NN; m++) {
                float4 av = *(const float4*)&sAm[m][k];
                acc[m] += av.x * bv.x + av.y * bv.y + av.z * bv.z + av.w * bv.w;
            }
        }
    }
#pragma unroll
    for (int off = 16; off; off >>= 1)
#pragma unroll
        for (int m = 0; m < NN; m++)
            acc[m] += __shfl_down_sync(0xffffffffu, acc[m], off);

    if (lane == 0 && n < N) {
        float bz = bias ? bias[n] : 0.f;
#pragma unroll
        for (int m = 0; m < NN; m++)
            C[(long long)m * ldc + n] = acc[m] + bz;
    }
}

// ---------------- fp32 tiled SGEMM (tiny final layer) ----------------
__global__ __launch_bounds__(256)
void sgemm_nt(int M, int N, int K,
              const float* __restrict__ A, long long lda,
              const float* __restrict__ B, long long ldb,
              float* __restrict__ C, long long ldc,
              const float* __restrict__ bias) {
    const int BM = 128, BN = 128, BK = 8;
    __shared__ float As[BK][BM];
    __shared__ float Bs[BK][BN];

    int m0 = blockIdx.y * BM;
    int n0 = blockIdx.x * BN;
    int tid = threadIdx.x;
    int tx = tid & 15, ty = tid >> 4;
    int arow = tid >> 1, acol = (tid & 1) * 4;
    int bnrow = tid >> 5, bncol = (tid & 31) * 4;

    float acc[8][8];
#pragma unroll
    for (int i = 0; i < 8; i++)
#pragma unroll
        for (int j = 0; j < 8; j++) acc[i][j] = 0.f;

    for (int k0 = 0; k0 < K; k0 += BK) {
        {
            int gm = m0 + arow, gk = k0 + acol;
            float4 v = make_float4(0.f, 0.f, 0.f, 0.f);
            if (gm < M && gk < K) {
                const float* p = A + (long long)gm * lda + gk;
                float t[4] = {0.f, 0.f, 0.f, 0.f};
#pragma unroll
                for (int i = 0; i < 4; i++) if (gk + i < K) t[i] = p[i];
                v = make_float4(t[0], t[1], t[2], t[3]);
            }
            As[acol + 0][arow] = v.x; As[acol + 1][arow] = v.y;
            As[acol + 2][arow] = v.z; As[acol + 3][arow] = v.w;
        }
        {
            int gk = k0 + bnrow, gj = n0 + bncol;
            float4 v = make_float4(0.f, 0.f, 0.f, 0.f);
            if (gk < K) {
                const float* p = B + (long long)gk * ldb + gj;
                float t[4] = {0.f, 0.f, 0.f, 0.f};
#pragma unroll
                for (int i = 0; i < 4; i++) if (gj + i < N) t[i] = p[i];
                v = make_float4(t[0], t[1], t[2], t[3]);
            }
            *(float4*)&Bs[bnrow][bncol] = v;
        }
        __syncthreads();

#pragma unroll
        for (int kk = 0; kk < BK; kk++) {
            float a[8], b[8];
#pragma unroll
            for (int i = 0; i < 8; i++) a[i] = As[kk][ty * 8 + i];
#pragma unroll
            for (int j = 0; j < 8; j++) b[j] = Bs[kk][tx * 8 + j];
#pragma unroll
            for (int i = 0; i < 8; i++)
#pragma unroll
                for (int j = 0; j < 8; j++) acc[i][j] = fmaf(a[i], b[j], acc[i][j]);
        }
        __syncthreads();
    }

#pragma unroll
    for (int i = 0; i < 8; i++) {
        int gm = m0 + ty * 8 + i;
        if (gm >= M) continue;
#pragma unroll
        for (int j = 0; j < 8; j++) {
            int gn = n0 + tx * 8 + j;
            if (gn >= N) continue;
            float v = acc[i][j];
            if (bias) v += bias[gn];
            C[(long long)gm * ldc + gn] = v;
        }
    }
}

// ------- fused softmax (rounded store for tensor-core consumer) ---
__global__ void softmax_fused(const float* __restrict__ S0,
                              const float* __restrict__ Bq,
                              float* __restrict__ attn, float scale) {
    int l = blockIdx.x;
    int n = blockIdx.y;
    const float* s0 = S0 + (long long)l * BB;
    const float* bq = Bq + (long long)n * BB;
    float* out = attn + ((long long)n * BB + l) * BB;

    int t = threadIdx.x;
    float v[4];
#pragma unroll
    for (int i = 0; i < 4; i++) {
        int m = t + i * 256;
        v[i] = scale * (s0[m] + bq[m]);
    }

    float mx = fmaxf(fmaxf(v[0], v[1]), fmaxf(v[2], v[3]));
#pragma unroll
    for (int o = 16; o; o >>= 1) mx = fmaxf(mx, __shfl_xor_sync(0xffffffffu, mx, o));
    __shared__ float sm[8];
    int lane = t & 31, wid = t >> 5;
    if (!lane) sm[wid] = mx;
    __syncthreads();
    if (t == 0) {
        float m = sm[0];
        for (int i = 1; i < 8; i++) m = fmaxf(m, sm[i]);
        sm[0] = m;
    }
    __syncthreads();
    mx = sm[0];

    float s = 0.f;
#pragma unroll
    for (int i = 0; i < 4; i++) { v[i] = __expf(v[i] - mx); s += v[i]; }
#pragma unroll
    for (int o = 16; o; o >>= 1) s += __shfl_xor_sync(0xffffffffu, s, o);
    __syncthreads();
    if (!lane) sm[wid] = s;
    __syncthreads();
    if (t == 0) {
        float a = 0.f;
        for (int i = 0; i < 8; i++) a += sm[i];
        sm[0] = a;
    }
    __syncthreads();
    float inv = 1.f / sm[0];
#pragma unroll
    for (int i = 0; i < 4; i++) out[t + i * 256] = tf32r(v[i] * inv);
}

// -------- LN1: x1 = LN(node + ao2); writes exact + rounded copies -----------
__global__ void ln1_kernel(const float* __restrict__ img, const float* __restrict__ we,
                           const float* __restrict__ R,
                           const float* __restrict__ g, const float* __restrict__ bb,
                           float* __restrict__ out, float* __restrict__ outr) {
    const int D = DD;
    long long row = blockIdx.x;
    int b = (int)(row / NN);
    int n = (int)(row % NN);
    __shared__ float buf[DD];
    __shared__ float w1s[8], w2s[8];
    const float* ig = img + (long long)b * IMG;
    const float* w  = we + (long long)n * TXT;
    const float* r  = R + row * D;
    float s = 0.f, s2 = 0.f;
    for (int i = threadIdx.x; i < D; i += 256) {
        float nd = (i < IMG) ? ig[i] : w[i - IMG];
        float v = nd + r[i];
        buf[i] = v;
        s += v; s2 += v * v;
    }
#pragma unroll
    for (int o = 16; o; o >>= 1) {
        s  += __shfl_down_sync(0xffffffffu, s, o);
        s2 += __shfl_down_sync(0xffffffffu, s2, o);
    }
    int lane = threadIdx.x & 31, wid = threadIdx.x >> 5;
    if (!lane) { w1s[wid] = s; w2s[wid] = s2; }
    __syncthreads();
    if (threadIdx.x == 0) {
        float a = 0.f, b2 = 0.f;
        for (int i = 0; i < 8; i++) { a += w1s[i]; b2 += w2s[i]; }
        w1s[0] = a; w2s[0] = b2;
    }
    __syncthreads();
    float mean = w1s[0] / D;
    float var  = w2s[0] / D - mean * mean;
    float inv  = rsqrtf(var + 1e-5f);
    float* o = out + row * D;
    float* orr = outr + row * D;
    for (int i = threadIdx.x; i < D; i += 256) {
        float v = (buf[i] - mean) * inv * g[i] + bb[i];
        o[i] = v;
        orr[i] = tf32r(v);
    }
}

// ---------------- LN2: x2 = round(LN(X + R)) ----------------
__global__ void ln_kernel(const float* __restrict__ X, const float* __restrict__ R,
                          const float* __restrict__ g, const float* __restrict__ bb,
                          float* __restrict__ out) {
    const int D = DD;
    long long row = blockIdx.x;
    __shared__ float buf[DD];
    __shared__ float w1s[8], w2s[8];
    const float* x = X + row * D;
    const float* r = R + row * D;
    float s = 0.f, s2 = 0.f;
    for (int i = threadIdx.x; i < D; i += 256) {
        float v = x[i] + r[i];
        buf[i] = v;
        s += v; s2 += v * v;
    }
#pragma unroll
    for (int o = 16; o; o >>= 1) {
        s  += __shfl_down_sync(0xffffffffu, s, o);
        s2 += __shfl_down_sync(0xffffffffu, s2, o);
    }
    int lane = threadIdx.x & 31, wid = threadIdx.x >> 5;
    if (!lane) { w1s[wid] = s; w2s[wid] = s2; }
    __syncthreads();
    if (threadIdx.x == 0) {
        float a = 0.f, b2 = 0.f;
        for (int i = 0; i < 8; i++) { a += w1s[i]; b2 += w2s[i]; }
        w1s[0] = a; w2s[0] = b2;
    }
    __syncthreads();
    float mean = w1s[0] / D;
    float var  = w2s[0] / D - mean * mean;
    float inv  = rsqrtf(var + 1e-5f);
    float* o = out + row * D;
    for (int i = threadIdx.x; i < D; i += 256)
        o[i] = tf32r((buf[i] - mean) * inv * g[i] + bb[i]);
}

// ---------------- GCN edge prep ----------------
__global__ void edge_prep(const int* __restrict__ ei) {
    if (threadIdx.x != 0 || blockIdx.x != 0) return;
    float deg[NN]; int cnt[NN];
    for (int n = 0; n < NN; n++) { deg[n] = 0.f; cnt[n] = 0; }
    for (int e = 0; e < EE; e++) { int d = ei[EE + e]; deg[d] += 1.f; cnt[d]++; }
    for (int n = 0; n < NN; n++) { deg[n] += 1.f; cnt[n]++; }
    float dinv[NN];
    for (int n = 0; n < NN; n++) dinv[n] = (deg[n] > 0.f) ? rsqrtf(deg[n]) : 0.f;
    int off = 0, pos[NN];
    for (int n = 0; n < NN; n++) { g_eoff[n] = off; pos[n] = off; off += cnt[n]; }
    g_eoff[NN] = off;
    for (int e = 0; e < EE; e++) {
        int d = ei[EE + e], s = ei[e];
        int p = pos[d]++;
        g_esrc[p] = s;
        g_ewt[p]  = dinv[s] * dinv[d];
    }
    for (int n = 0; n < NN; n++) {
        int p = pos[n]++;
        g_esrc[p] = n;
        g_ewt[p]  = dinv[n] * dinv[n];
    }
}

// ---------------- GCN scatter-aggregate ----------------
__global__ void gcn_agg(const float* __restrict__ hin, const float* __restrict__ bias,
                        float* __restrict__ out, int relu, int round_out) {
    int b   = blockIdx.x / NN;
    int dst = blockIdx.x % NN;
    int h   = threadIdx.x;
    const float* base = hin + (long long)b * NN * HID;
    float acc = bias[h];
    int e0 = g_eoff[dst], e1 = g_eoff[dst + 1];
    for (int e = e0; e < e1; e++)
        acc += g_ewt[e] * base[g_esrc[e] * HID + h];
    if (relu) acc = fmaxf(acc, 0.f);
    if (round_out) acc = tf32r(acc);
    out[((long long)b * NN + dst) * HID + h] = acc;
}

// ---------------- mean over nodes + relu ----------------
__global__ void pool_kernel(const float* __restrict__ g, float* __restrict__ out) {
    int idx = blockIdx.x * blockDim.x + threadIdx.x;
    if (idx >= BB * HID) return;
    int b = idx >> 7, h = idx & 127;
    const float* p = g + (long long)b * NN * HID + h;
    float s = 0.f;
#pragma unroll
    for (int n = 0; n < NN; n++) s += p[n * HID];
    s *= (1.f / (float)NN);
    out[idx] = fmaxf(s, 0.f);
}

// ---------------- launch ----------------
static inline int ceil_div(int a, int b) { return (a + b - 1) / b; }

extern "C" void kernel_launch(void* const* d_in, const int* in_sizes, int n_in,
                              void* d_out, int out_size) {
    const float* img   = (const float*)d_in[0];
    const float* we    = (const float*)d_in[1];
    const int*   ei    = (const int*)  d_in[2];
    const float* inw   = (const float*)d_in[3];
    const float* inb   = (const float*)d_in[4];
    const float* outw  = (const float*)d_in[5];
    const float* outb  = (const float*)d_in[6];
    const float* ln1g  = (const float*)d_in[7];
    const float* ln1b  = (const float*)d_in[8];
    const float* ln2g  = (const float*)d_in[9];
    const float* ln2b  = (const float*)d_in[10];
    const float* w1    = (const float*)d_in[11];
    const float* b1    = (const float*)d_in[12];
    const float* w2    = (const float*)d_in[13];
    const float* b2    = (const float*)d_in[14];
    const float* gw1   = (const float*)d_in[15];
    const float* gb1   = (const float*)d_in[16];
    const float* gw2   = (const float*)d_in[17];
    const float* gb2   = (const float*)d_in[18];
    const float* lw    = (const float*)d_in[19];
    const float* lb    = (const float*)d_in[20];
    float* out = (float*)d_out;

    float *qkvi, *qkvt, *S0, *Bq, *Vo, *ovt, *attn, *ao2, *x1, *x1r, *hid, *ff, *x2;
    float *g1, *g2, *g3, *g4, *pool;
    float *imgr, *inwr, *outwr, *w1r, *w2r, *gw1r, *gw2r;
    cudaGetSymbolAddress((void**)&qkvi, g_qkvi);
    cudaGetSymbolAddress((void**)&qkvt, g_qkvt);
    cudaGetSymbolAddress((void**)&S0,   g_S0);
    cudaGetSymbolAddress((void**)&Bq,   g_Bq);
    cudaGetSymbolAddress((void**)&Vo,   g_Vo);
    cudaGetSymbolAddress((void**)&ovt,  g_ovt);
    cudaGetSymbolAddress((void**)&attn, g_attn);
    cudaGetSymbolAddress((void**)&ao2,  g_ao2);
    cudaGetSymbolAddress((void**)&x1,   g_x1);
    cudaGetSymbolAddress((void**)&x1r,  g_x1r);
    cudaGetSymbolAddress((void**)&hid,  g_hid);
    cudaGetSymbolAddress((void**)&ff,   g_ff);
    cudaGetSymbolAddress((void**)&x2,   g_x2);
    cudaGetSymbolAddress((void**)&g1,   g_g1);
    cudaGetSymbolAddress((void**)&g2,   g_g2);
    cudaGetSymbolAddress((void**)&g3,   g_g3);
    cudaGetSymbolAddress((void**)&g4,   g_g4);
    cudaGetSymbolAddress((void**)&pool, g_pool);
    cudaGetSymbolAddress((void**)&imgr, g_imgr);
    cudaGetSymbolAddress((void**)&inwr, g_inwr);
    cudaGetSymbolAddress((void**)&outwr, g_outwr);
    cudaGetSymbolAddress((void**)&w1r,  g_w1r);
    cudaGetSymbolAddress((void**)&w2r,  g_w2r);
    cudaGetSymbolAddress((void**)&gw1r, g_gw1r);
    cudaGetSymbolAddress((void**)&gw2r, g_gw2r);

    cudaFuncSetAttribute(tg256<true>,
                         cudaFuncAttributeMaxDynamicSharedMemorySize, C4_SMEM);
    cudaFuncSetAttribute(tg256<false>,
                         cudaFuncAttributeMaxDynamicSharedMemorySize, C4_SMEM);
    cudaFuncSetAttribute(tg512<true>,
                         cudaFuncAttributeMaxDynamicSharedMemorySize, C5_SMEM);
    cudaFuncSetAttribute(tg512<false>,
                         cudaFuncAttributeMaxDynamicSharedMemorySize, C5_SMEM);

    const float attn_scale = 1.0f / sqrtf((float)DD);

    // 0) round-copy all tensor-core operand weights in ONE launch
    {
        RCTab tab;
        tab.s[0] = { img, imgr, (long long)BB * IMG / 4 };
        tab.s[1] = { inw, inwr, (long long)D3 * DD / 4 };
        tab.s[2] = { outw, outwr, (long long)DD * DD / 4 };
        tab.s[3] = { w1, w1r, (long long)DD * FF / 4 };
        tab.s[4] = { w2, w2r, (long long)FF * DD / 4 };
        tab.s[5] = { gw1, gw1r, (long long)DD * HID / 4 };
        tab.s[6] = { gw2, gw2r, (long long)HID * HID / 4 };
        long long tot = 0;
        for (int k = 0; k < 7; k++) tot += tab.s[k].n4;
        round_copy_multi<<<(unsigned)((tot + 255) / 256), 256>>>(tab);
    }

    // 1) qkvi = imgr @ inwr[:, :512]^T  (1024 x 2436)   [tg512, grid 160]
    tg512<true><<<dim3(ceil_div(D3, 128), 8, 1), 512, C5_SMEM>>>(
        BB, D3, IMG, imgr, IMG, 0, inwr, DD, 0, qkvi, D3, 0, nullptr, 0, 1.f, 0, 1);
    // 2) qkvt (thin, fp32)
    thin_gemm_bt<<<ceil_div(D3, 8), 256>>>(
        D3, TXT, we, TXT, inw + IMG, DD, qkvt, D3, inb);
    // 3) S0 = qi @ ki^T (1024 x 1024)   [tg256, grid 128]
    tg256<true><<<dim3(8, 16, 1), 256, C4_SMEM>>>(
        BB, BB, DD, qkvi, D3, 0, qkvi + DD, D3, 0, S0, BB, 0, nullptr, 0, 1.f, 0, 0);
    // 4) Bq (thin)
    thin_gemm_bt<<<ceil_div(BB, 8), 256>>>(
        BB, DD, qkvt, D3, qkvi + DD, D3, Bq, BB, nullptr);
    // 5) Vo = vi @ Wout^T (1024 x 812)  [tg256, grid 112]
    tg256<true><<<dim3(ceil_div(DD, 128), 16, 1), 256, C4_SMEM>>>(
        BB, DD, DD, qkvi + 2 * DD, D3, 0, outwr, DD, 0, Vo, DD, 0, nullptr, 0, 1.f, 0, 1);
    // 6) ovt (thin)
    thin_gemm_bt<<<ceil_div(DD, 8), 256>>>(
        DD, DD, qkvt + 2 * DD, D3, outw, DD, ovt, DD, outb);
    // 7) attn = softmax(scale*(S0 + Bq)), rounded
    softmax_fused<<<dim3(BB, NN), 256>>>(S0, Bq, attn, attn_scale);
    // 8) ao2[l,n,:] = attn_n @ Vo + ovt[n]   [tg512, grid 784]
    tg512<false><<<dim3(ceil_div(DD, 128), 8, NN), 512, C5_SMEM>>>(
        BB, DD, BB,
        attn, BB, (long long)BB * BB,
        Vo, DD, 0,
        ao2, (long long)NN * DD, DD,
        ovt, DD, 1.f, 0, 0);
    // 9) x1 = LN(node + ao2); x1r rounded
    ln1_kernel<<<MM, 256>>>(img, we, ao2, ln1g, ln1b, x1, x1r);
    // 10) hid = relu(x1r @ w1r + b1)   [tg512, grid 1792]
    tg512<false><<<dim3(ceil_div(FF, 128), ceil_div(MM, 128), 1), 512, C5_SMEM>>>(
        MM, FF, DD, x1r, DD, 0, w1r, FF, 0, hid, FF, 0, b1, 0, 1.f, 1, 1);
    // 11) ff = hid @ w2r + b2          [tg512, grid 784]
    tg512<false><<<dim3(ceil_div(DD, 128), ceil_div(MM, 128), 1), 512, C5_SMEM>>>(
        MM, DD, FF, hid, FF, 0, w2r, DD, 0, ff, DD, 0, b2, 0, 1.f, 0, 0);
    // 12) x2 = round(LN(x1 + ff))
    ln_kernel<<<MM, 256>>>(x1, ff, ln2g, ln2b, x2);
    // 13) edge prep
    edge_prep<<<1, 32>>>(ei);
    // 14) g1 = x2 @ gw1r               [tg256, grid 224]
    tg256<false><<<dim3(1, ceil_div(MM, 64), 1), 256, C4_SMEM>>>(
        MM, HID, DD, x2, DD, 0, gw1r, HID, 0, g1, HID, 0, nullptr, 0, 1.f, 0, 0);
    // 15) g2 = relu(agg(g1) + gb1), rounded
    gcn_agg<<<MM, HID>>>(g1, gb1, g2, 1, 1);
    // 16) g3 = g2 @ gw2r               [tg256, grid 224]
    tg256<false><<<dim3(1, ceil_div(MM, 64), 1), 256, C4_SMEM>>>(
        MM, HID, HID, g2, HID, 0, gw2r, HID, 0, g3, HID, 0, nullptr, 0, 1.f, 0, 0);
    // 17) g4 = agg(g3) + gb2
    gcn_agg<<<MM, HID>>>(g3, gb2, g4, 0, 0);
    // 18) pool = relu(mean over nodes)
    pool_kernel<<<(BB * HID + 255) / 256, 256>>>(g4, pool);
    // 19) out = pool @ lin_w + lin_b (fp32)
    sgemm_nt<<<dim3(1, ceil_div(BB, 128), 1), 256>>>(
        BB, CC, HID, pool, HID, lw, CC, out, CC, lb);
}

// round 11
// speedup vs baseline: 1.2270x; 1.2270x over previous
#include <cuda_runtime.h>
#include <cstdint>
#include <math.h>

// ---------------- problem constants ----------------
#define BB   1024
#define IMG  512
#define TXT  300
#define NN   14
#define FF   2048
#define HID  128
#define CC   14
#define EE   182
#define DD   812     // IMG + TXT
#define D3   2436    // 3*D
#define MM   (BB*NN) // 14336 rows

// ---------------- scratch (device globals; no allocation) ----------------
__device__ float g_qkvi[(size_t)BB * D3];
__device__ float g_qkvt[(size_t)NN * D3];
__device__ float g_S0  [(size_t)BB * BB];
__device__ float g_Bq  [(size_t)NN * BB];
__device__ float g_Vo  [(size_t)BB * DD];
__device__ float g_ovt [(size_t)NN * DD];
__device__ float g_attn[(size_t)NN * BB * BB];
__device__ float g_ao2 [(size_t)MM * DD];
__device__ float g_x1  [(size_t)MM * DD];
__device__ float g_x1r [(size_t)MM * DD];
__device__ float g_hid [(size_t)MM * FF];
__device__ float g_ff  [(size_t)MM * DD];
__device__ float g_x2  [(size_t)MM * DD];
__device__ float g_g1  [(size_t)MM * HID];
__device__ float g_g2  [(size_t)MM * HID];
__device__ float g_g3  [(size_t)MM * HID];
__device__ float g_g4  [(size_t)MM * HID];
__device__ float g_pool[(size_t)BB * HID];

// rounded copies
__device__ float g_imgr [(size_t)BB * IMG];
__device__ float g_inwr [(size_t)D3 * DD];
__device__ float g_outwr[(size_t)DD * DD];
__device__ float g_w1r  [(size_t)DD * FF];
__device__ float g_w2r  [(size_t)FF * DD];
__device__ float g_gw1r [(size_t)DD * HID];
__device__ float g_gw2r [(size_t)HID * HID];

__device__ int   g_eoff[NN + 1];
__device__ int   g_esrc[EE + NN + 16];
__device__ float g_ewt [EE + NN + 16];

__device__ __forceinline__ float tf32r(float f) {
    uint32_t r;
    asm("cvt.rna.tf32.f32 %0, %1;" : "=r"(r) : "f"(f));
    return __uint_as_float(r);
}

// ================= TF32 mma.sync GEMM (cp.async, 3-stage) ===================
// (R7-proven config) CTA tile (IM*64) x 128, BK=16, 256 threads (8 warps 4x2).
// IM=2: 128x128 (warp 32x64); IM=1: 64x128 (warp 16x64).
#define CA_STAGES 3

template <int IM> struct CAC {
    static const int A_U32 = IM * 64 * 20;
    static const int STAGE_U32 = A_U32 + 2560;
    static const int SMEM = CA_STAGES * STAGE_U32 * 4;
};

template <bool BT, int IM>
__device__ __forceinline__ void ca_fetch(
    int k0, int M, int N, int K,
    const float* __restrict__ A, long long lda,
    const float* __restrict__ B, long long ldb,
    int m0, int n0, int tid, uint32_t sA_addr, uint32_t sB_addr) {
    if (IM == 2) {
        int arow = tid >> 1, acol = (tid & 1) * 8;
        int gm = m0 + arow;
        bool mv = gm < M;
        const float* rowp = A + (long long)(mv ? gm : m0) * lda;
#pragma unroll
        for (int h = 0; h < 2; h++) {
            int gk = k0 + acol + h * 4;
            int rem = K - gk;
            int vb = mv ? (rem >= 4 ? 16 : (rem > 0 ? rem * 4 : 0)) : 0;
            const float* src = rowp + (gk < K ? gk : 0);
            uint32_t dst = sA_addr + (uint32_t)(arow * 20 + acol + h * 4) * 4u;
            asm volatile("cp.async.cg.shared.global [%0], [%1], 16, %2;"
                         :: "r"(dst), "l"(src), "r"(vb));
        }
    } else {
        int arow = tid >> 2, acol = (tid & 3) * 4;
        int gm = m0 + arow;
        bool mv = gm < M;
        const float* rowp = A + (long long)(mv ? gm : m0) * lda;
        int gk = k0 + acol;
        int rem = K - gk;
        int vb = mv ? (rem >= 4 ? 16 : (rem > 0 ? rem * 4 : 0)) : 0;
        const float* src = rowp + (gk < K ? gk : 0);
        uint32_t dst = sA_addr + (uint32_t)(arow * 20 + acol) * 4u;
        asm volatile("cp.async.cg.shared.global [%0], [%1], 16, %2;"
                     :: "r"(dst), "l"(src), "r"(vb));
    }
    if (BT) {
        int arow = tid >> 1, acol = (tid & 1) * 8;
        int gj = n0 + arow;
        bool nv = gj < N;
        const float* rowp = B + (long long)(nv ? gj : n0) * ldb;
#pragma unroll
        for (int h = 0; h < 2; h++) {
            int gk = k0 + acol + h * 4;
            int rem = K - gk;
            int vb = nv ? (rem >= 4 ? 16 : (rem > 0 ? rem * 4 : 0)) : 0;
            const float* src = rowp + (gk < K ? gk : 0);
            uint32_t dst = sB_addr + (uint32_t)(arow * 20 + acol + h * 4) * 4u;
            asm volatile("cp.async.cg.shared.global [%0], [%1], 16, %2;"
                         :: "r"(dst), "l"(src), "r"(vb));
        }
    } else {
        int bkrow = tid >> 4, bncol = (tid & 15) * 8;
        int gk = k0 + bkrow;
        bool kv = gk < K;
        const float* rowp = B + (long long)(kv ? gk : k0) * ldb;
#pragma unroll
        for (int h = 0; h < 2; h++) {
            int gj = n0 + bncol + h * 4;
            int rem = N - gj;
            int vb = kv ? (rem >= 4 ? 16 : (rem > 0 ? rem * 4 : 0)) : 0;
            const float* src = rowp + (gj < N ? gj : 0);
            uint32_t dst = sB_addr + (uint32_t)(bkrow * 136 + bncol + h * 4) * 4u;
            asm volatile("cp.async.cg.shared.global [%0], [%1], 16, %2;"
                         :: "r"(dst), "l"(src), "r"(vb));
        }
    }
}

template <bool BT, int IM>
__device__ __forceinline__ void tg_core(
    int M, int N, int K,
    const float* __restrict__ A, long long lda,
    const float* __restrict__ B, long long ldb,
    float* __restrict__ C, long long ldc,
    const float* __restrict__ bias,
    float alpha, int relu, int round_out,
    int m0, int n0, uint32_t* dsm) {
    int tid = threadIdx.x;
    int warp = tid >> 5, lane = tid & 31;
    int wm = warp >> 1, wn = warp & 1;
    int gid = lane >> 2, tig = lane & 3;

    uint32_t smem_base = (uint32_t)__cvta_generic_to_shared(dsm);

    float c[IM][8][4];
#pragma unroll
    for (int i = 0; i < IM; i++)
#pragma unroll
        for (int j = 0; j < 8; j++)
#pragma unroll
            for (int r = 0; r < 4; r++) c[i][j][r] = 0.f;

    int ntiles = (K + 15) >> 4;

#pragma unroll
    for (int t = 0; t < CA_STAGES - 1; t++) {
        if (t < ntiles) {
            uint32_t sa = smem_base + (uint32_t)(t * CAC<IM>::STAGE_U32) * 4u;
            ca_fetch<BT, IM>(t * 16, M, N, K, A, lda, B, ldb, m0, n0, tid,
                             sa, sa + (uint32_t)CAC<IM>::A_U32 * 4u);
        }
        asm volatile("cp.async.commit_group;");
    }

    for (int t = 0; t < ntiles; t++) {
        asm volatile("cp.async.wait_group %0;" :: "n"(CA_STAGES - 2));
        __syncthreads();

        int nf = t + CA_STAGES - 1;
        if (nf < ntiles) {
            uint32_t sa = smem_base +
                (uint32_t)((nf % CA_STAGES) * CAC<IM>::STAGE_U32) * 4u;
            ca_fetch<BT, IM>(nf * 16, M, N, K, A, lda, B, ldb, m0, n0, tid,
                             sa, sa + (uint32_t)CAC<IM>::A_U32 * 4u);
        }
        asm volatile("cp.async.commit_group;");

        const uint32_t* sAu = dsm + (t % CA_STAGES) * CAC<IM>::STAGE_U32;
        const uint32_t* sBu = sAu + CAC<IM>::A_U32;

#pragma unroll
        for (int ks = 0; ks < 16; ks += 8) {
            uint32_t a[IM][4], b[8][2];
#pragma unroll
            for (int i = 0; i < IM; i++) {
                int mb = wm * (IM * 16) + i * 16 + gid;
                a[i][0] = sAu[mb * 20 + ks + tig];
                a[i][1] = sAu[(mb + 8) * 20 + ks + tig];
                a[i][2] = sAu[mb * 20 + ks + tig + 4];
                a[i][3] = sAu[(mb + 8) * 20 + ks + tig + 4];
            }
#pragma unroll
            for (int j = 0; j < 8; j++) {
                int nb = wn * 64 + j * 8 + gid;
                if (BT) {
                    b[j][0] = sBu[nb * 20 + ks + tig];
                    b[j][1] = sBu[nb * 20 + ks + tig + 4];
                } else {
                    b[j][0] = sBu[(ks + tig) * 136 + nb];
                    b[j][1] = sBu[(ks + tig + 4) * 136 + nb];
                }
            }
#pragma unroll
            for (int i = 0; i < IM; i++)
#pragma unroll
                for (int j = 0; j < 8; j++) {
                    asm volatile(
                        "mma.sync.aligned.m16n8k8.row.col.f32.tf32.tf32.f32 "
                        "{%0,%1,%2,%3}, {%4,%5,%6,%7}, {%8,%9}, {%0,%1,%2,%3};"
                        : "+f"(c[i][j][0]), "+f"(c[i][j][1]),
                          "+f"(c[i][j][2]), "+f"(c[i][j][3])
                        : "r"(a[i][0]), "r"(a[i][1]), "r"(a[i][2]), "r"(a[i][3]),
                          "r"(b[j][0]), "r"(b[j][1]));
                }
        }
    }

#pragma unroll
    for (int i = 0; i < IM; i++) {
        int r0 = m0 + wm * (IM * 16) + i * 16 + gid;
#pragma unroll
        for (int j = 0; j < 8; j++) {
            int c0 = n0 + wn * 64 + j * 8 + 2 * tig;
#pragma unroll
            for (int rr = 0; rr < 2; rr++) {
                int gm = r0 + rr * 8;
                if (gm >= M) continue;
#pragma unroll
                for (int cc = 0; cc < 2; cc++) {
                    int gn = c0 + cc;
                    if (gn >= N) continue;
                    float v = c[i][j][rr * 2 + cc] * alpha;
                    if (bias) v += bias[gn];
                    if (relu) v = fmaxf(v, 0.f);
                    if (round_out) v = tf32r(v);
                    C[(long long)gm * ldc + gn] = v;
                }
            }
        }
    }
}

template <bool BT, int IM>
__global__ __launch_bounds__(256, 2)
void tgemm_ca(int M, int N, int K,
              const float* __restrict__ A, long long lda, long long sA,
              const float* __restrict__ B, long long ldb, long long sB,
              float* __restrict__ C, long long ldc, long long sC,
              const float* __restrict__ bias, long long sBias,
              float alpha, int relu, int round_out) {
    extern __shared__ uint32_t dsm[];
    int z = blockIdx.z;
    A += (long long)z * sA;
    B += (long long)z * sB;
    C += (long long)z * sC;
    if (bias) bias += (long long)z * sBias;
    tg_core<BT, IM>(M, N, K, A, lda, B, ldb, C, ldc, bias,
                    alpha, relu, round_out,
                    blockIdx.y * (IM * 64), blockIdx.x * 128, dsm);
}

// ---- dual GEMM (two independent BT/IM=1 GEMMs in one launch, z selects) ----
struct GArgs {
    const float* A; const float* B; float* C; const float* bias;
    long long lda, ldb, ldc;
    int M, N, K, nbx, relu, round_out;
    float alpha;
};

__global__ __launch_bounds__(256, 2)
void tg_dual_bt1(GArgs a0, GArgs a1) {
    extern __shared__ uint32_t dsm[];
    const GArgs& g = (blockIdx.z == 0) ? a0 : a1;
    if ((int)blockIdx.x >= g.nbx) return;
    tg_core<true, 1>(g.M, g.N, g.K, g.A, g.lda, g.B, g.ldb, g.C, g.ldc, g.bias,
                     g.alpha, g.relu, g.round_out,
                     blockIdx.y * 64, blockIdx.x * 128, dsm);
}

// ================= thin GEMM body (M == 14) =================
__device__ __forceinline__ void thin_body(
    int bid, int N, int K,
    const float* __restrict__ A, long long lda,
    const float* __restrict__ B, long long ldb,
    float* __restrict__ C, long long ldc,
    const float* __restrict__ bias, float* sAm /* [NN][816] */) {
    int tid = threadIdx.x;
    int K4 = K >> 2;
    for (int idx = tid; idx < NN * K4; idx += 256) {
        int m = idx / K4, k4 = idx - m * K4;
        *(float4*)&sAm[m * 816 + k4 * 4] =
            *(const float4*)(A + (long long)m * lda + k4 * 4);
    }
    __syncthreads();

    int n = bid * 8 + (tid >> 5);
    int lane = tid & 31;
    float acc[NN];
#pragma unroll
    for (int m = 0; m < NN; m++) acc[m] = 0.f;

    if (n < N) {
        const float* Bp = B + (long long)n * ldb;
        for (int k = lane * 4; k + 4 <= K; k += 128) {
            float4 bv = *(const float4*)(Bp + k);
#pragma unroll
            for (int m = 0; m < NN; m++) {
                float4 av = *(const float4*)&sAm[m * 816 + k];
                acc[m] += av.x * bv.x + av.y * bv.y + av.z * bv.z + av.w * bv.w;
            }
        }
    }
#pragma unroll
    for (int off = 16; off; off >>= 1)
#pragma unroll
        for (int m = 0; m < NN; m++)
            acc[m] += __shfl_down_sync(0xffffffffu, acc[m], off);

    if (lane == 0 && n < N) {
        float bz = bias ? bias[n] : 0.f;
#pragma unroll
        for (int m = 0; m < NN; m++)
            C[(long long)m * ldc + n] = acc[m] + bz;
    }
}

// ---- fused prep: round_copy(7 segs) + qkvt thin + edge_prep, one launch ----
struct RCSeg { const float* src; float* dst; long long n4; };
struct PrepArgs {
    RCSeg s[7];
    int nb_rc;                 // #blocks for round-copy
    const float* we; const float* inw; const float* inb; float* qkvt;
    const int* ei;
};

__global__ __launch_bounds__(256)
void prep_kernel(PrepArgs pa) {
    __shared__ float sAm[NN * 816];
    int bid = blockIdx.x;
    if (bid < pa.nb_rc) {
        long long i = (long long)bid * 256 + threadIdx.x;
#pragma unroll
        for (int k = 0; k < 7; k++) {
            if (i < pa.s[k].n4) {
                float4 v = *(const float4*)(pa.s[k].src + i * 4);
                v.x = tf32r(v.x); v.y = tf32r(v.y);
                v.z = tf32r(v.z); v.w = tf32r(v.w);
                *(float4*)(pa.s[k].dst + i * 4) = v;
                return;
            }
            i -= pa.s[k].n4;
        }
        return;
    }
    int tb = bid - pa.nb_rc;
    const int NB_QKVT = (D3 + 7) / 8;
    if (tb < NB_QKVT) {
        // qkvt = we @ inw[:,512:]^T + inb   (14 x 2436)
        thin_body(tb, D3, TXT, pa.we, TXT, pa.inw + IMG, DD,
                  pa.qkvt, D3, pa.inb, sAm);
        return;
    }
    // edge prep (single block, thread 0)
    if (threadIdx.x != 0) return;
    const int* ei = pa.ei;
    float deg[NN]; int cnt[NN];
    for (int n = 0; n < NN; n++) { deg[n] = 0.f; cnt[n] = 0; }
    for (int e = 0; e < EE; e++) { int d = ei[EE + e]; deg[d] += 1.f; cnt[d]++; }
    for (int n = 0; n < NN; n++) { deg[n] += 1.f; cnt[n]++; }
    float dinv[NN];
    for (int n = 0; n < NN; n++) dinv[n] = (deg[n] > 0.f) ? rsqrtf(deg[n]) : 0.f;
    int off = 0, pos[NN];
    for (int n = 0; n < NN; n++) { g_eoff[n] = off; pos[n] = off; off += cnt[n]; }
    g_eoff[NN] = off;
    for (int e = 0; e < EE; e++) {
        int d = ei[EE + e], s = ei[e];
        int p = pos[d]++;
        g_esrc[p] = s;
        g_ewt[p]  = dinv[s] * dinv[d];
    }
    for (int n = 0; n < NN; n++) {
        int p = pos[n]++;
        g_esrc[p] = n;
        g_ewt[p]  = dinv[n] * dinv[n];
    }
}

// ---- fused thin pair: Bq + ovt in one launch (block ranges) ----
struct TPairArgs {
    int nb0;
    int N0, K0; const float* A0; long long lda0; const float* B0; long long ldb0;
    float* C0; long long ldc0; const float* bias0;
    int N1, K1; const float* A1; long long lda1; const float* B1; long long ldb1;
    float* C1; long long ldc1; const float* bias1;
};

__global__ __launch_bounds__(256)
void thin_pair(TPairArgs t) {
    __shared__ float sAm[NN * 816];
    int bid = blockIdx.x;
    if (bid < t.nb0)
        thin_body(bid, t.N0, t.K0, t.A0, t.lda0, t.B0, t.ldb0,
                  t.C0, t.ldc0, t.bias0, sAm);
    else
        thin_body(bid - t.nb0, t.N1, t.K1, t.A1, t.lda1, t.B1, t.ldb1,
                  t.C1, t.ldc1, t.bias1, sAm);
}

// ---------------- fp32 tiled SGEMM (tiny final layer) ----------------
__global__ __launch_bounds__(256)
void sgemm_nt(int M, int N, int K,
              const float* __restrict__ A, long long lda,
              const float* __restrict__ B, long long ldb,
              float* __restrict__ C, long long ldc,
              const float* __restrict__ bias) {
    const int BM = 128, BN = 128, BK = 8;
    __shared__ float As[BK][BM];
    __shared__ float Bs[BK][BN];

    int m0 = blockIdx.y * BM;
    int n0 = blockIdx.x * BN;
    int tid = threadIdx.x;
    int tx = tid & 15, ty = tid >> 4;
    int arow = tid >> 1, acol = (tid & 1) * 4;
    int bnrow = tid >> 5, bncol = (tid & 31) * 4;

    float acc[8][8];
#pragma unroll
    for (int i = 0; i < 8; i++)
#pragma unroll
        for (int j = 0; j < 8; j++) acc[i][j] = 0.f;

    for (int k0 = 0; k0 < K; k0 += BK) {
        {
            int gm = m0 + arow, gk = k0 + acol;
            float4 v = make_float4(0.f, 0.f, 0.f, 0.f);
            if (gm < M && gk < K) {
                const float* p = A + (long long)gm * lda + gk;
                float t[4] = {0.f, 0.f, 0.f, 0.f};
#pragma unroll
                for (int i = 0; i < 4; i++) if (gk + i < K) t[i] = p[i];
                v = make_float4(t[0], t[1], t[2], t[3]);
            }
            As[acol + 0][arow] = v.x; As[acol + 1][arow] = v.y;
            As[acol + 2][arow] = v.z; As[acol + 3][arow] = v.w;
        }
        {
            int gk = k0 + bnrow, gj = n0 + bncol;
            float4 v = make_float4(0.f, 0.f, 0.f, 0.f);
            if (gk < K) {
                const float* p = B + (long long)gk * ldb + gj;
                float t[4] = {0.f, 0.f, 0.f, 0.f};
#pragma unroll
                for (int i = 0; i < 4; i++) if (gj + i < N) t[i] = p[i];
                v = make_float4(t[0], t[1], t[2], t[3]);
            }
            *(float4*)&Bs[bnrow][bncol] = v;
        }
        __syncthreads();

#pragma unroll
        for (int kk = 0; kk < BK; kk++) {
            float a[8], b[8];
#pragma unroll
            for (int i = 0; i < 8; i++) a[i] = As[kk][ty * 8 + i];
#pragma unroll
            for (int j = 0; j < 8; j++) b[j] = Bs[kk][tx * 8 + j];
#pragma unroll
            for (int i = 0; i < 8; i++)
#pragma unroll
                for (int j = 0; j < 8; j++) acc[i][j] = fmaf(a[i], b[j], acc[i][j]);
        }
        __syncthreads();
    }

#pragma unroll
    for (int i = 0; i < 8; i++) {
        int gm = m0 + ty * 8 + i;
        if (gm >= M) continue;
#pragma unroll
        for (int j = 0; j < 8; j++) {
            int gn = n0 + tx * 8 + j;
            if (gn >= N) continue;
            float v = acc[i][j];
            if (bias) v += bias[gn];
            C[(long long)gm * ldc + gn] = v;
        }
    }
}

// ------- fused softmax (rounded store) ---
__global__ void softmax_fused(const float* __restrict__ S0,
                              const float* __restrict__ Bq,
                              float* __restrict__ attn, float scale) {
    int l = blockIdx.x;
    int n = blockIdx.y;
    const float* s0 = S0 + (long long)l * BB;
    const float* bq = Bq + (long long)n * BB;
    float* out = attn + ((long long)n * BB + l) * BB;

    int t = threadIdx.x;
    float v[4];
#pragma unroll
    for (int i = 0; i < 4; i++) {
        int m = t + i * 256;
        v[i] = scale * (s0[m] + bq[m]);
    }

    float mx = fmaxf(fmaxf(v[0], v[1]), fmaxf(v[2], v[3]));
#pragma unroll
    for (int o = 16; o; o >>= 1) mx = fmaxf(mx, __shfl_xor_sync(0xffffffffu, mx, o));
    __shared__ float sm[8];
    int lane = t & 31, wid = t >> 5;
    if (!lane) sm[wid] = mx;
    __syncthreads();
    if (t == 0) {
        float m = sm[0];
        for (int i = 1; i < 8; i++) m = fmaxf(m, sm[i]);
        sm[0] = m;
    }
    __syncthreads();
    mx = sm[0];

    float s = 0.f;
#pragma unroll
    for (int i = 0; i < 4; i++) { v[i] = __expf(v[i] - mx); s += v[i]; }
#pragma unroll
    for (int o = 16; o; o >>= 1) s += __shfl_xor_sync(0xffffffffu, s, o);
    __syncthreads();
    if (!lane) sm[wid] = s;
    __syncthreads();
    if (t == 0) {
        float a = 0.f;
        for (int i = 0; i < 8; i++) a += sm[i];
        sm[0] = a;
    }
    __syncthreads();
    float inv = 1.f / sm[0];
#pragma unroll
    for (int i = 0; i < 4; i++) out[t + i * 256] = tf32r(v[i] * inv);
}

// -------- LN1: x1 = LN(node + ao2); exact + rounded copies -----------
__global__ void ln1_kernel(const float* __restrict__ img, const float* __restrict__ we,
                           const float* __restrict__ R,
                           const float* __restrict__ g, const float* __restrict__ bb,
                           float* __restrict__ out, float* __restrict__ outr) {
    const int D = DD;
    long long row = blockIdx.x;
    int b = (int)(row / NN);
    int n = (int)(row % NN);
    __shared__ float buf[DD];
    __shared__ float w1s[8], w2s[8];
    const float* ig = img + (long long)b * IMG;
    const float* w  = we + (long long)n * TXT;
    const float* r  = R + row * D;
    float s = 0.f, s2 = 0.f;
    for (int i = threadIdx.x; i < D; i += 256) {
        float nd = (i < IMG) ? ig[i] : w[i - IMG];
        float v = nd + r[i];
        buf[i] = v;
        s += v; s2 += v * v;
    }
#pragma unroll
    for (int o = 16; o; o >>= 1) {
        s  += __shfl_down_sync(0xffffffffu, s, o);
        s2 += __shfl_down_sync(0xffffffffu, s2, o);
    }
    int lane = threadIdx.x & 31, wid = threadIdx.x >> 5;
    if (!lane) { w1s[wid] = s; w2s[wid] = s2; }
    __syncthreads();
    if (threadIdx.x == 0) {
        float a = 0.f, b2 = 0.f;
        for (int i = 0; i < 8; i++) { a += w1s[i]; b2 += w2s[i]; }
        w1s[0] = a; w2s[0] = b2;
    }
    __syncthreads();
    float mean = w1s[0] / D;
    float var  = w2s[0] / D - mean * mean;
    float inv  = rsqrtf(var + 1e-5f);
    float* o = out + row * D;
    float* orr = outr + row * D;
    for (int i = threadIdx.x; i < D; i += 256) {
        float v = (buf[i] - mean) * inv * g[i] + bb[i];
        o[i] = v;
        orr[i] = tf32r(v);
    }
}

// ---------------- LN2: x2 = round(LN(X + R)) ----------------
__global__ void ln_kernel(const float* __restrict__ X, const float* __restrict__ R,
                          const float* __restrict__ g, const float* __restrict__ bb,
                          float* __restrict__ out) {
    const int D = DD;
    long long row = blockIdx.x;
    __shared__ float buf[DD];
    __shared__ float w1s[8], w2s[8];
    const float* x = X + row * D;
    const float* r = R + row * D;
    float s = 0.f, s2 = 0.f;
    for (int i = threadIdx.x; i < D; i += 256) {
        float v = x[i] + r[i];
        buf[i] = v;
        s += v; s2 += v * v;
    }
#pragma unroll
    for (int o = 16; o; o >>= 1) {
        s  += __shfl_down_sync(0xffffffffu, s, o);
        s2 += __shfl_down_sync(0xffffffffu, s2, o);
    }
    int lane = threadIdx.x & 31, wid = threadIdx.x >> 5;
    if (!lane) { w1s[wid] = s; w2s[wid] = s2; }
    __syncthreads();
    if (threadIdx.x == 0) {
        float a = 0.f, b2 = 0.f;
        for (int i = 0; i < 8; i++) { a += w1s[i]; b2 += w2s[i]; }
        w1s[0] = a; w2s[0] = b2;
    }
    __syncthreads();
    float mean = w1s[0] / D;
    float var  = w2s[0] / D - mean * mean;
    float inv  = rsqrtf(var + 1e-5f);
    float* o = out + row * D;
    for (int i = threadIdx.x; i < D; i += 256)
        o[i] = tf32r((buf[i] - mean) * inv * g[i] + bb[i]);
}

// ---------------- GCN scatter-aggregate ----------------
__global__ void gcn_agg(const float* __restrict__ hin, const float* __restrict__ bias,
                        float* __restrict__ out, int relu, int round_out) {
    int b   = blockIdx.x / NN;
    int dst = blockIdx.x % NN;
    int h   = threadIdx.x;
    const float* base = hin + (long long)b * NN * HID;
    float acc = bias[h];
    int e0 = g_eoff[dst], e1 = g_eoff[dst + 1];
    for (int e = e0; e < e1; e++)
        acc += g_ewt[e] * base[g_esrc[e] * HID + h];
    if (relu) acc = fmaxf(acc, 0.f);
    if (round_out) acc = tf32r(acc);
    out[((long long)b * NN + dst) * HID + h] = acc;
}

// ---------------- mean over nodes + relu ----------------
__global__ void pool_kernel(const float* __restrict__ g, float* __restrict__ out) {
    int idx = blockIdx.x * blockDim.x + threadIdx.x;
    if (idx >= BB * HID) return;
    int b = idx >> 7, h = idx & 127;
    const float* p = g + (long long)b * NN * HID + h;
    float s = 0.f;
#pragma unroll
    for (int n = 0; n < NN; n++) s += p[n * HID];
    s *= (1.f / (float)NN);
    out[idx] = fmaxf(s, 0.f);
}

// ---------------- launch ----------------
static inline int ceil_div(int a, int b) { return (a + b - 1) / b; }

extern "C" void kernel_launch(void* const* d_in, const int* in_sizes, int n_in,
                              void* d_out, int out_size) {
    const float* img   = (const float*)d_in[0];
    const float* we    = (const float*)d_in[1];
    const int*   ei    = (const int*)  d_in[2];
    const float* inw   = (const float*)d_in[3];
    const float* inb   = (const float*)d_in[4];
    const float* outw  = (const float*)d_in[5];
    const float* outb  = (const float*)d_in[6];
    const float* ln1g  = (const float*)d_in[7];
    const float* ln1b  = (const float*)d_in[8];
    const float* ln2g  = (const float*)d_in[9];
    const float* ln2b  = (const float*)d_in[10];
    const float* w1    = (const float*)d_in[11];
    const float* b1    = (const float*)d_in[12];
    const float* w2    = (const float*)d_in[13];
    const float* b2    = (const float*)d_in[14];
    const float* gw1   = (const float*)d_in[15];
    const float* gb1   = (const float*)d_in[16];
    const float* gw2   = (const float*)d_in[17];
    const float* gb2   = (const float*)d_in[18];
    const float* lw    = (const float*)d_in[19];
    const float* lb    = (const float*)d_in[20];
    float* out = (float*)d_out;

    float *qkvi, *qkvt, *S0, *Bq, *Vo, *ovt, *attn, *ao2, *x1, *x1r, *hid, *ff, *x2;
    float *g1, *g2, *g3, *g4, *pool;
    float *imgr, *inwr, *outwr, *w1r, *w2r, *gw1r, *gw2r;
    cudaGetSymbolAddress((void**)&qkvi, g_qkvi);
    cudaGetSymbolAddress((void**)&qkvt, g_qkvt);
    cudaGetSymbolAddress((void**)&S0,   g_S0);
    cudaGetSymbolAddress((void**)&Bq,   g_Bq);
    cudaGetSymbolAddress((void**)&Vo,   g_Vo);
    cudaGetSymbolAddress((void**)&ovt,  g_ovt);
    cudaGetSymbolAddress((void**)&attn, g_attn);
    cudaGetSymbolAddress((void**)&ao2,  g_ao2);
    cudaGetSymbolAddress((void**)&x1,   g_x1);
    cudaGetSymbolAddress((void**)&x1r,  g_x1r);
    cudaGetSymbolAddress((void**)&hid,  g_hid);
    cudaGetSymbolAddress((void**)&ff,   g_ff);
    cudaGetSymbolAddress((void**)&x2,   g_x2);
    cudaGetSymbolAddress((void**)&g1,   g_g1);
    cudaGetSymbolAddress((void**)&g2,   g_g2);
    cudaGetSymbolAddress((void**)&g3,   g_g3);
    cudaGetSymbolAddress((void**)&g4,   g_g4);
    cudaGetSymbolAddress((void**)&pool, g_pool);
    cudaGetSymbolAddress((void**)&imgr, g_imgr);
    cudaGetSymbolAddress((void**)&inwr, g_inwr);
    cudaGetSymbolAddress((void**)&outwr, g_outwr);
    cudaGetSymbolAddress((void**)&w1r,  g_w1r);
    cudaGetSymbolAddress((void**)&w2r,  g_w2r);
    cudaGetSymbolAddress((void**)&gw1r, g_gw1r);
    cudaGetSymbolAddress((void**)&gw2r, g_gw2r);

    cudaFuncSetAttribute(tgemm_ca<true, 2>,
                         cudaFuncAttributeMaxDynamicSharedMemorySize, CAC<2>::SMEM);
    cudaFuncSetAttribute(tgemm_ca<false, 2>,
                         cudaFuncAttributeMaxDynamicSharedMemorySize, CAC<2>::SMEM);
    cudaFuncSetAttribute(tgemm_ca<true, 1>,
                         cudaFuncAttributeMaxDynamicSharedMemorySize, CAC<1>::SMEM);
    cudaFuncSetAttribute(tgemm_ca<false, 1>,
                         cudaFuncAttributeMaxDynamicSharedMemorySize, CAC<1>::SMEM);
    cudaFuncSetAttribute(tg_dual_bt1,
                         cudaFuncAttributeMaxDynamicSharedMemorySize, CAC<1>::SMEM);

    const float attn_scale = 1.0f / sqrtf((float)DD);

    // 0) PREP: round-copy (7 segs) + qkvt thin-GEMM + edge_prep, ONE launch
    {
        PrepArgs pa;
        pa.s[0] = { img, imgr, (long long)BB * IMG / 4 };
        pa.s[1] = { inw, inwr, (long long)D3 * DD / 4 };
        pa.s[2] = { outw, outwr, (long long)DD * DD / 4 };
        pa.s[3] = { w1, w1r, (long long)DD * FF / 4 };
        pa.s[4] = { w2, w2r, (long long)FF * DD / 4 };
        pa.s[5] = { gw1, gw1r, (long long)DD * HID / 4 };
        pa.s[6] = { gw2, gw2r, (long long)HID * HID / 4 };
        long long tot = 0;
        for (int k = 0; k < 7; k++) tot += pa.s[k].n4;
        pa.nb_rc = (int)((tot + 255) / 256);
        pa.we = we; pa.inw = inw; pa.inb = inb; pa.qkvt = qkvt; pa.ei = ei;
        int nblocks = pa.nb_rc + ceil_div(D3, 8) + 1;
        prep_kernel<<<nblocks, 256>>>(pa);
    }

    // 1) qkvi = imgr @ inwr[:, :512]^T  (1024 x 2436)  [IM=2, grid 160]
    tgemm_ca<true, 2><<<dim3(ceil_div(D3, 128), 8, 1), 256, CAC<2>::SMEM>>>(
        BB, D3, IMG, imgr, IMG, 0, inwr, DD, 0, qkvi, D3, 0, nullptr, 0, 1.f, 0, 1);

    // 2) DUAL: S0 = qi@ki^T  ||  Vo = vi@Wout^T   (one launch, z selects)
    {
        GArgs a0, a1;
        a0.A = qkvi; a0.lda = D3; a0.B = qkvi + DD; a0.ldb = D3;
        a0.C = S0; a0.ldc = BB; a0.bias = nullptr;
        a0.M = BB; a0.N = BB; a0.K = DD; a0.nbx = 8;
        a0.relu = 0; a0.round_out = 0; a0.alpha = 1.f;
        a1.A = qkvi + 2 * DD; a1.lda = D3; a1.B = outwr; a1.ldb = DD;
        a1.C = Vo; a1.ldc = DD; a1.bias = nullptr;
        a1.M = BB; a1.N = DD; a1.K = DD; a1.nbx = ceil_div(DD, 128);
        a1.relu = 0; a1.round_out = 1; a1.alpha = 1.f;
        tg_dual_bt1<<<dim3(8, 16, 2), 256, CAC<1>::SMEM>>>(a0, a1);
    }

    // 3) DUAL thin: Bq = qt@ki^T  ||  ovt = vt@Wout^T + outb
    {
        TPairArgs tp;
        tp.nb0 = ceil_div(BB, 8);
        tp.N0 = BB; tp.K0 = DD; tp.A0 = qkvt; tp.lda0 = D3;
        tp.B0 = qkvi + DD; tp.ldb0 = D3; tp.C0 = Bq; tp.ldc0 = BB; tp.bias0 = nullptr;
        tp.N1 = DD; tp.K1 = DD; tp.A1 = qkvt + 2 * DD; tp.lda1 = D3;
        tp.B1 = outw; tp.ldb1 = DD; tp.C1 = ovt; tp.ldc1 = DD; tp.bias1 = outb;
        thin_pair<<<tp.nb0 + ceil_div(DD, 8), 256>>>(tp);
    }

    // 4) attn = softmax(scale*(S0 + Bq)), rounded
    softmax_fused<<<dim3(BB, NN), 256>>>(S0, Bq, attn, attn_scale);
    // 5) ao2[l,n,:] = attn_n @ Vo + ovt[n]   [IM=2, batched]
    tgemm_ca<false, 2><<<dim3(ceil_div(DD, 128), 8, NN), 256, CAC<2>::SMEM>>>(
        BB, DD, BB,
        attn, BB, (long long)BB * BB,
        Vo, DD, 0,
        ao2, (long long)NN * DD, DD,
        ovt, DD, 1.f, 0, 0);
    // 6) x1 = LN(node + ao2); x1r rounded
    ln1_kernel<<<MM, 256>>>(img, we, ao2, ln1g, ln1b, x1, x1r);
    // 7) hid = relu(x1r @ w1r + b1)   [IM=2]
    tgemm_ca<false, 2><<<dim3(ceil_div(FF, 128), ceil_div(MM, 128), 1), 256, CAC<2>::SMEM>>>(
        MM, FF, DD, x1r, DD, 0, w1r, FF, 0, hid, FF, 0, b1, 0, 1.f, 1, 1);
    // 8) ff = hid @ w2r + b2          [IM=2]
    tgemm_ca<false, 2><<<dim3(ceil_div(DD, 128), ceil_div(MM, 128), 1), 256, CAC<2>::SMEM>>>(
        MM, DD, FF, hid, FF, 0, w2r, DD, 0, ff, DD, 0, b2, 0, 1.f, 0, 0);
    // 9) x2 = round(LN(x1 + ff))
    ln_kernel<<<MM, 256>>>(x1, ff, ln2g, ln2b, x2);
    // 10) g1 = x2 @ gw1r              [IM=1, grid 224]
    tgemm_ca<false, 1><<<dim3(1, ceil_div(MM, 64), 1), 256, CAC<1>::SMEM>>>(
        MM, HID, DD, x2, DD, 0, gw1r, HID, 0, g1, HID, 0, nullptr, 0, 1.f, 0, 0);
    // 11) g2 = relu(agg(g1) + gb1), rounded
    gcn_agg<<<MM, HID>>>(g1, gb1, g2, 1, 1);
    // 12) g3 = g2 @ gw2r              [IM=1]
    tgemm_ca<false, 1><<<dim3(1, ceil_div(MM, 64), 1), 256, CAC<1>::SMEM>>>(
        MM, HID, HID, g2, HID, 0, gw2r, HID, 0, g3, HID, 0, nullptr, 0, 1.f, 0, 0);
    // 13) g4 = agg(g3) + gb2
    gcn_agg<<<MM, HID>>>(g3, gb2, g4, 0, 0);
    // 14) pool = relu(mean over nodes)
    pool_kernel<<<(BB * HID + 255) / 256, 256>>>(g4, pool);
    // 15) out = pool @ lin_w + lin_b (fp32)
    sgemm_nt<<<dim3(1, ceil_div(BB, 128), 1), 256>>>(
        BB, CC, HID, pool, HID, lw, CC, out, CC, lb);
}

// round 12
// speedup vs baseline: 1.8758x; 1.5287x over previous
#include <cuda_runtime.h>
#include <cuda_fp16.h>
#include <cstdint>
#include <math.h>

// ---------------- problem constants ----------------
#define BB   1024
#define IMG  512
#define TXT  300
#define NN   14
#define FF   2048
#define HID  128
#define CC   14
#define EE   182
#define DD   812     // IMG + TXT
#define D3   2436    // 3*D
#define MM   (BB*NN) // 14336 rows
#define DP   816     // DD padded to mult of 8
#define QLD  2448    // 3*DP, qkv fp16 row stride

// ---------------- fp32 scratch ----------------
__device__ float g_qkvi[(size_t)BB * D3];
__device__ float g_qkvt[(size_t)NN * D3];
__device__ float g_S0  [(size_t)BB * BB];
__device__ float g_Bq  [(size_t)NN * BB];
__device__ float g_ovt [(size_t)NN * DD];
__device__ float g_ao2 [(size_t)MM * DD];
__device__ float g_x1  [(size_t)MM * DD];
__device__ float g_ff  [(size_t)MM * DD];
__device__ float g_g1  [(size_t)MM * HID];
__device__ float g_g3  [(size_t)MM * HID];
__device__ float g_g4  [(size_t)MM * HID];
__device__ float g_pool[(size_t)BB * HID];

// ---------------- fp16 scratch (tensor-core operands) ----------------
__device__ __align__(256) __half g_imgr_h [(size_t)BB * IMG];
__device__ __align__(256) __half g_inwr_h [(size_t)D3 * IMG];
__device__ __align__(256) __half g_outwr_h[(size_t)DD * DP];
__device__ __align__(256) __half g_qkvi_h [(size_t)BB * QLD];
__device__ __align__(256) __half g_VoT_h  [(size_t)DD * BB];
__device__ __align__(256) __half g_attn_h [(size_t)NN * BB * BB];
__device__ __align__(256) __half g_x1r_h  [(size_t)MM * DP];
__device__ __align__(256) __half g_w1t_h  [(size_t)FF * DP];
__device__ __align__(256) __half g_hid_h  [(size_t)MM * FF];
__device__ __align__(256) __half g_w2t_h  [(size_t)DD * FF];
__device__ __align__(256) __half g_x2_h   [(size_t)MM * DP];
__device__ __align__(256) __half g_gw1t_h [(size_t)HID * DP];
__device__ __align__(256) __half g_g2_h   [(size_t)MM * HID];
__device__ __align__(256) __half g_gw2t_h [(size_t)HID * HID];

__device__ int   g_eoff[NN + 1];
__device__ int   g_esrc[EE + NN + 16];
__device__ float g_ewt [EE + NN + 16];

// ================= fp16 mma.sync GEMM (cp.async, 3-stage, BT only) ==========
// C[m,n] = sum_k A[m,k]*B[n,k] (+bias, relu).  A:[M][K] fp16, B:[N][K] fp16,
// both rows 16B-aligned.  CTA tile (IM*64)x128, BK=32 halves, 256 threads,
// 8 warps (4x2), warp tile (IM*16)x64.  smem rows: 20 u32 (16 data + 4 pad).
#define CA_STAGES 3
template <int IM> struct CAC {
    static const int A_U32 = IM * 64 * 20;
    static const int STAGE_U32 = A_U32 + 2560;   // B: 128*20
    static const int SMEM = CA_STAGES * STAGE_U32 * 4;
};

template <int IM>
__device__ __forceinline__ void hfetch(
    int k0, int M, int N, int K,
    const __half* __restrict__ A, long long lda,
    const __half* __restrict__ B, long long ldb,
    int m0, int n0, int tid, uint32_t sA, uint32_t sB) {
    if (IM == 2) {
        int row = tid >> 1, c = tid & 1;
        int gm = m0 + row;
        bool mv = gm < M;
        const __half* rp = A + (long long)(mv ? gm : m0) * lda;
#pragma unroll
        for (int h = 0; h < 2; h++) {
            int kh = k0 + c * 16 + h * 8;
            int rem = K - kh;
            int vb = mv ? (rem >= 8 ? 16 : (rem > 0 ? rem * 2 : 0)) : 0;
            const __half* src = rp + (kh < K ? kh : 0);
            uint32_t dst = sA + (uint32_t)(row * 20 + c * 8 + h * 4) * 4u;
            asm volatile("cp.async.cg.shared.global [%0], [%1], 16, %2;"
                         :: "r"(dst), "l"(src), "r"(vb));
        }
    } else {
        int row = tid >> 2, c = tid & 3;
        int gm = m0 + row;
        bool mv = gm < M;
        const __half* rp = A + (long long)(mv ? gm : m0) * lda;
        int kh = k0 + c * 8;
        int rem = K - kh;
        int vb = mv ? (rem >= 8 ? 16 : (rem > 0 ? rem * 2 : 0)) : 0;
        const __half* src = rp + (kh < K ? kh : 0);
        uint32_t dst = sA + (uint32_t)(row * 20 + c * 4) * 4u;
        asm volatile("cp.async.cg.shared.global [%0], [%1], 16, %2;"
                     :: "r"(dst), "l"(src), "r"(vb));
    }
    {
        int row = tid >> 1, c = tid & 1;
        int gj = n0 + row;
        bool nv = gj < N;
        const __half* rp = B + (long long)(nv ? gj : n0) * ldb;
#pragma unroll
        for (int h = 0; h < 2; h++) {
            int kh = k0 + c * 16 + h * 8;
            int rem = K - kh;
            int vb = nv ? (rem >= 8 ? 16 : (rem > 0 ? rem * 2 : 0)) : 0;
            const __half* src = rp + (kh < K ? kh : 0);
            uint32_t dst = sB + (uint32_t)(row * 20 + c * 8 + h * 4) * 4u;
            asm volatile("cp.async.cg.shared.global [%0], [%1], 16, %2;"
                         :: "r"(dst), "l"(src), "r"(vb));
        }
    }
}

template <int IM>
__device__ __forceinline__ void hg_core(
    int M, int N, int K,
    const __half* __restrict__ A, long long lda,
    const __half* __restrict__ B, long long ldb,
    float* __restrict__ C, long long ldc,
    __half* __restrict__ Ch, long long ldh,
    const float* __restrict__ bias,
    int relu, int qkvpad,
    int m0, int n0, uint32_t* dsm) {
    if (m0 >= M) return;
    int tid = threadIdx.x;
    int warp = tid >> 5, lane = tid & 31;
    int wm = warp >> 1, wn = warp & 1;
    int gid = lane >> 2, tig = lane & 3;

    uint32_t smem_base = (uint32_t)__cvta_generic_to_shared(dsm);

    float c[IM][8][4];
#pragma unroll
    for (int i = 0; i < IM; i++)
#pragma unroll
        for (int j = 0; j < 8; j++)
#pragma unroll
            for (int r = 0; r < 4; r++) c[i][j][r] = 0.f;

    int ntiles = (K + 31) >> 5;

#pragma unroll
    for (int t = 0; t < CA_STAGES - 1; t++) {
        if (t < ntiles) {
            uint32_t sa = smem_base + (uint32_t)(t * CAC<IM>::STAGE_U32) * 4u;
            hfetch<IM>(t * 32, M, N, K, A, lda, B, ldb, m0, n0, tid,
                       sa, sa + (uint32_t)CAC<IM>::A_U32 * 4u);
        }
        asm volatile("cp.async.commit_group;");
    }

    for (int t = 0; t < ntiles; t++) {
        asm volatile("cp.async.wait_group %0;" :: "n"(CA_STAGES - 2));
        __syncthreads();

        int nf = t + CA_STAGES - 1;
        if (nf < ntiles) {
            uint32_t sa = smem_base +
                (uint32_t)((nf % CA_STAGES) * CAC<IM>::STAGE_U32) * 4u;
            hfetch<IM>(nf * 32, M, N, K, A, lda, B, ldb, m0, n0, tid,
                       sa, sa + (uint32_t)CAC<IM>::A_U32 * 4u);
        }
        asm volatile("cp.async.commit_group;");

        const uint32_t* sAu = dsm + (t % CA_STAGES) * CAC<IM>::STAGE_U32;
        const uint32_t* sBu = sAu + CAC<IM>::A_U32;

#pragma unroll
        for (int ks = 0; ks < 2; ks++) {
            int ku = ks * 8;
            uint32_t a[IM][4], b[8][2];
#pragma unroll
            for (int i = 0; i < IM; i++) {
                int mb = wm * (IM * 16) + i * 16 + gid;
                a[i][0] = sAu[mb * 20 + ku + tig];
                a[i][1] = sAu[(mb + 8) * 20 + ku + tig];
                a[i][2] = sAu[mb * 20 + ku + tig + 4];
                a[i][3] = sAu[(mb + 8) * 20 + ku + tig + 4];
            }
#pragma unroll
            for (int j = 0; j < 8; j++) {
                int nb = wn * 64 + j * 8 + gid;
                b[j][0] = sBu[nb * 20 + ku + tig];
                b[j][1] = sBu[nb * 20 + ku + tig + 4];
            }
#pragma unroll
            for (int i = 0; i < IM; i++)
#pragma unroll
                for (int j = 0; j < 8; j++) {
                    asm volatile(
                        "mma.sync.aligned.m16n8k16.row.col.f32.f16.f16.f32 "
                        "{%0,%1,%2,%3}, {%4,%5,%6,%7}, {%8,%9}, {%0,%1,%2,%3};"
                        : "+f"(c[i][j][0]), "+f"(c[i][j][1]),
                          "+f"(c[i][j][2]), "+f"(c[i][j][3])
                        : "r"(a[i][0]), "r"(a[i][1]), "r"(a[i][2]), "r"(a[i][3]),
                          "r"(b[j][0]), "r"(b[j][1]));
                }
        }
    }

    // ---- epilogue ----
#pragma unroll
    for (int i = 0; i < IM; i++) {
        int r0 = m0 + wm * (IM * 16) + i * 16 + gid;
#pragma unroll
        for (int j = 0; j < 8; j++) {
            int c0 = n0 + wn * 64 + j * 8 + 2 * tig;
#pragma unroll
            for (int rr = 0; rr < 2; rr++) {
                int gm = r0 + rr * 8;
                if (gm >= M) continue;
#pragma unroll
                for (int cc = 0; cc < 2; cc++) {
                    int gn = c0 + cc;
                    if (gn >= N) continue;
                    float v = c[i][j][rr * 2 + cc];
                    if (bias) v += bias[gn];
                    if (relu) v = fmaxf(v, 0.f);
                    if (C) C[(long long)gm * ldc + gn] = v;
                    if (Ch) {
                        int col = gn;
                        if (qkvpad) {
                            int seg = (gn >= 2 * DD) ? 2 : (gn >= DD ? 1 : 0);
                            col = seg * DP + (gn - seg * DD);
                        }
                        Ch[(long long)gm * ldh + col] = __float2half_rn(v);
                    }
                }
            }
        }
    }
}

template <int IM>
__global__ __launch_bounds__(256, 2)
void hgemm(int M, int N, int K,
           const __half* __restrict__ A, long long lda, long long sA,
           const __half* __restrict__ B, long long ldb, long long sB,
           float* __restrict__ C, long long ldc, long long sC,
           __half* __restrict__ Ch, long long ldh, long long sCh,
           const float* __restrict__ bias, long long sBias,
           int relu, int qkvpad) {
    extern __shared__ uint32_t dsm[];
    int z = blockIdx.z;
    A += (long long)z * sA;
    B += (long long)z * sB;
    if (C) C += (long long)z * sC;
    if (Ch) Ch += (long long)z * sCh;
    if (bias) bias += (long long)z * sBias;
    hg_core<IM>(M, N, K, A, lda, B, ldb, C, ldc, Ch, ldh, bias,
                relu, qkvpad, blockIdx.y * (IM * 64), blockIdx.x * 128, dsm);
}

// ---- dual fp16 GEMM (S0 || VoT), IM=1, z selects ----
struct HG {
    const __half* A; const __half* B; float* C; __half* Ch;
    long long lda, ldb, ldc, ldh;
    int M, N, K;
};

__global__ __launch_bounds__(256, 2)
void hg_dual(HG a0, HG a1) {
    extern __shared__ uint32_t dsm[];
    const HG& g = (blockIdx.z == 0) ? a0 : a1;
    hg_core<1>(g.M, g.N, g.K, g.A, g.lda, g.B, g.ldb, g.C, g.ldc,
               g.Ch, g.ldh, nullptr, 0, 0,
               blockIdx.y * 64, blockIdx.x * 128, dsm);
}

// ================= thin GEMM body (M == 14, fp32) =================
__device__ __forceinline__ void thin_body(
    int bid, int N, int K,
    const float* __restrict__ A, long long lda,
    const float* __restrict__ B, long long ldb,
    float* __restrict__ C, long long ldc,
    const float* __restrict__ bias, float* sAm) {
    int tid = threadIdx.x;
    int K4 = K >> 2;
    for (int idx = tid; idx < NN * K4; idx += 256) {
        int m = idx / K4, k4 = idx - m * K4;
        *(float4*)&sAm[m * 816 + k4 * 4] =
            *(const float4*)(A + (long long)m * lda + k4 * 4);
    }
    __syncthreads();

    int n = bid * 8 + (tid >> 5);
    int lane = tid & 31;
    float acc[NN];
#pragma unroll
    for (int m = 0; m < NN; m++) acc[m] = 0.f;

    if (n < N) {
        const float* Bp = B + (long long)n * ldb;
        for (int k = lane * 4; k + 4 <= K; k += 128) {
            float4 bv = *(const float4*)(Bp + k);
#pragma unroll
            for (int m = 0; m < NN; m++) {
                float4 av = *(const float4*)&sAm[m * 816 + k];
                acc[m] += av.x * bv.x + av.y * bv.y + av.z * bv.z + av.w * bv.w;
            }
        }
    }
#pragma unroll
    for (int off = 16; off; off >>= 1)
#pragma unroll
        for (int m = 0; m < NN; m++)
            acc[m] += __shfl_down_sync(0xffffffffu, acc[m], off);

    if (lane == 0 && n < N) {
        float bz = bias ? bias[n] : 0.f;
#pragma unroll
        for (int m = 0; m < NN; m++)
            C[(long long)m * ldc + n] = acc[m] + bz;
    }
}

// ---- prep: fp16 converts (3 segs) + qkvt thin + edge_prep, one launch ----
struct CSeg { const float* src; __half* dst; int scols, ccols, dld; long long total; };
struct PrepArgs {
    CSeg s[3];
    int nb[3];
    const float* we; const float* inw; const float* inb; float* qkvt;
    const int* ei;
};

__global__ __launch_bounds__(256)
void prep_kernel(PrepArgs pa) {
    __shared__ float sAm[NN * 816];
    int bid = blockIdx.x;
#pragma unroll
    for (int k = 0; k < 3; k++) {
        if (bid < pa.nb[k]) {
            const CSeg& s = pa.s[k];
            long long base = (long long)bid * 1024 + threadIdx.x * 4;
#pragma unroll
            for (int e = 0; e < 4; e++) {
                long long i = base + e;
                if (i < s.total) {
                    int r = (int)(i / s.ccols), c = (int)(i % s.ccols);
                    s.dst[(long long)r * s.dld + c] =
                        __float2half_rn(s.src[(long long)r * s.scols + c]);
                }
            }
            return;
        }
        bid -= pa.nb[k];
    }
    const int NB_QKVT = (D3 + 7) / 8;
    if (bid < NB_QKVT) {
        thin_body(bid, D3, TXT, pa.we, TXT, pa.inw + IMG, DD,
                  pa.qkvt, D3, pa.inb, sAm);
        return;
    }
    if (threadIdx.x != 0) return;
    const int* ei = pa.ei;
    float deg[NN]; int cnt[NN];
    for (int n = 0; n < NN; n++) { deg[n] = 0.f; cnt[n] = 0; }
    for (int e = 0; e < EE; e++) { int d = ei[EE + e]; deg[d] += 1.f; cnt[d]++; }
    for (int n = 0; n < NN; n++) { deg[n] += 1.f; cnt[n]++; }
    float dinv[NN];
    for (int n = 0; n < NN; n++) dinv[n] = (deg[n] > 0.f) ? rsqrtf(deg[n]) : 0.f;
    int off = 0, pos[NN];
    for (int n = 0; n < NN; n++) { g_eoff[n] = off; pos[n] = off; off += cnt[n]; }
    g_eoff[NN] = off;
    for (int e = 0; e < EE; e++) {
        int d = ei[EE + e], s = ei[e];
        int p = pos[d]++;
        g_esrc[p] = s;
        g_ewt[p]  = dinv[s] * dinv[d];
    }
    for (int n = 0; n < NN; n++) {
        int p = pos[n]++;
        g_esrc[p] = n;
        g_ewt[p]  = dinv[n] * dinv[n];
    }
}

// ---- transpose + fp16: dst[c][r] = fp16(src[r][c]) ----
__global__ void transpose_h(const float* __restrict__ src, __half* __restrict__ dst,
                            int R, int Cc, int dld) {
    __shared__ float t[32][33];
    int c0 = blockIdx.x * 32, r0 = blockIdx.y * 32;
    int x = threadIdx.x, y = threadIdx.y;   // 32 x 8
#pragma unroll
    for (int j = 0; j < 4; j++) {
        int r = r0 + y + j * 8;
        if (r < R && c0 + x < Cc) t[y + j * 8][x] = src[(long long)r * Cc + c0 + x];
    }
    __syncthreads();
#pragma unroll
    for (int j = 0; j < 4; j++) {
        int c = c0 + y + j * 8;
        if (c < Cc && r0 + x < R)
            dst[(long long)c * dld + r0 + x] = __float2half_rn(t[x][y + j * 8]);
    }
}

// ---- fused thin pair: Bq + ovt ----
struct TPairArgs {
    int nb0;
    int N0, K0; const float* A0; long long lda0; const float* B0; long long ldb0;
    float* C0; long long ldc0; const float* bias0;
    int N1, K1; const float* A1; long long lda1; const float* B1; long long ldb1;
    float* C1; long long ldc1; const float* bias1;
};

__global__ __launch_bounds__(256)
void thin_pair(TPairArgs t) {
    __shared__ float sAm[NN * 816];
    int bid = blockIdx.x;
    if (bid < t.nb0)
        thin_body(bid, t.N0, t.K0, t.A0, t.lda0, t.B0, t.ldb0,
                  t.C0, t.ldc0, t.bias0, sAm);
    else
        thin_body(bid - t.nb0, t.N1, t.K1, t.A1, t.lda1, t.B1, t.ldb1,
                  t.C1, t.ldc1, t.bias1, sAm);
}

// ---------------- fp32 tiled SGEMM (tiny final layer) ----------------
__global__ __launch_bounds__(256)
void sgemm_nt(int M, int N, int K,
              const float* __restrict__ A, long long lda,
              const float* __restrict__ B, long long ldb,
              float* __restrict__ C, long long ldc,
              const float* __restrict__ bias) {
    const int BM = 128, BN = 128, BK = 8;
    __shared__ float As[BK][BM];
    __shared__ float Bs[BK][BN];

    int m0 = blockIdx.y * BM;
    int n0 = blockIdx.x * BN;
    int tid = threadIdx.x;
    int tx = tid & 15, ty = tid >> 4;
    int arow = tid >> 1, acol = (tid & 1) * 4;
    int bnrow = tid >> 5, bncol = (tid & 31) * 4;

    float acc[8][8];
#pragma unroll
    for (int i = 0; i < 8; i++)
#pragma unroll
        for (int j = 0; j < 8; j++) acc[i][j] = 0.f;

    for (int k0 = 0; k0 < K; k0 += BK) {
        {
            int gm = m0 + arow, gk = k0 + acol;
            float4 v = make_float4(0.f, 0.f, 0.f, 0.f);
            if (gm < M && gk < K) {
                const float* p = A + (long long)gm * lda + gk;
                float t[4] = {0.f, 0.f, 0.f, 0.f};
#pragma unroll
                for (int i = 0; i < 4; i++) if (gk + i < K) t[i] = p[i];
                v = make_float4(t[0], t[1], t[2], t[3]);
            }
            As[acol + 0][arow] = v.x; As[acol + 1][arow] = v.y;
            As[acol + 2][arow] = v.z; As[acol + 3][arow] = v.w;
        }
        {
            int gk = k0 + bnrow, gj = n0 + bncol;
            float4 v = make_float4(0.f, 0.f, 0.f, 0.f);
            if (gk < K) {
                const float* p = B + (long long)gk * ldb + gj;
                float t[4] = {0.f, 0.f, 0.f, 0.f};
#pragma unroll
                for (int i = 0; i < 4; i++) if (gj + i < N) t[i] = p[i];
                v = make_float4(t[0], t[1], t[2], t[3]);
            }
            *(float4*)&Bs[bnrow][bncol] = v;
        }
        __syncthreads();

#pragma unroll
        for (int kk = 0; kk < BK; kk++) {
            float a[8], b[8];
#pragma unroll
            for (int i = 0; i < 8; i++) a[i] = As[kk][ty * 8 + i];
#pragma unroll
            for (int j = 0; j < 8; j++) b[j] = Bs[kk][tx * 8 + j];
#pragma unroll
            for (int i = 0; i < 8; i++)
#pragma unroll
                for (int j = 0; j < 8; j++) acc[i][j] = fmaf(a[i], b[j], acc[i][j]);
        }
        __syncthreads();
    }

#pragma unroll
    for (int i = 0; i < 8; i++) {
        int gm = m0 + ty * 8 + i;
        if (gm >= M) continue;
#pragma unroll
        for (int j = 0; j < 8; j++) {
            int gn = n0 + tx * 8 + j;
            if (gn >= N) continue;
            float v = acc[i][j];
            if (bias) v += bias[gn];
            C[(long long)gm * ldc + gn] = v;
        }
    }
}

// ------- fused softmax (fp16 store) ---
__global__ void softmax_fused(const float* __restrict__ S0,
                              const float* __restrict__ Bq,
                              __half* __restrict__ attn, float scale) {
    int l = blockIdx.x;
    int n = blockIdx.y;
    const float* s0 = S0 + (long long)l * BB;
    const float* bq = Bq + (long long)n * BB;
    __half* out = attn + ((long long)n * BB + l) * BB;

    int t = threadIdx.x;
    float v[4];
#pragma unroll
    for (int i = 0; i < 4; i++) {
        int m = t + i * 256;
        v[i] = scale * (s0[m] + bq[m]);
    }

    float mx = fmaxf(fmaxf(v[0], v[1]), fmaxf(v[2], v[3]));
#pragma unroll
    for (int o = 16; o; o >>= 1) mx = fmaxf(mx, __shfl_xor_sync(0xffffffffu, mx, o));
    __shared__ float sm[8];
    int lane = t & 31, wid = t >> 5;
    if (!lane) sm[wid] = mx;
    __syncthreads();
    if (t == 0) {
        float m = sm[0];
        for (int i = 1; i < 8; i++) m = fmaxf(m, sm[i]);
        sm[0] = m;
    }
    __syncthreads();
    mx = sm[0];

    float s = 0.f;
#pragma unroll
    for (int i = 0; i < 4; i++) { v[i] = __expf(v[i] - mx); s += v[i]; }
#pragma unroll
    for (int o = 16; o; o >>= 1) s += __shfl_xor_sync(0xffffffffu, s, o);
    __syncthreads();
    if (!lane) sm[wid] = s;
    __syncthreads();
    if (t == 0) {
        float a = 0.f;
        for (int i = 0; i < 8; i++) a += sm[i];
        sm[0] = a;
    }
    __syncthreads();
    float inv = 1.f / sm[0];
#pragma unroll
    for (int i = 0; i < 4; i++)
        out[t + i * 256] = __float2half_rn(v[i] * inv);
}

// -------- LN1: x1 = LN(node + ao2); fp32 + fp16 copies -----------
__global__ void ln1_kernel(const float* __restrict__ img, const float* __restrict__ we,
                           const float* __restrict__ R,
                           const float* __restrict__ g, const float* __restrict__ bb,
                           float* __restrict__ out, __half* __restrict__ outh) {
    const int D = DD;
    long long row = blockIdx.x;
    int b = (int)(row / NN);
    int n = (int)(row % NN);
    __shared__ float buf[DD];
    __shared__ float w1s[8], w2s[8];
    const float* ig = img + (long long)b * IMG;
    const float* w  = we + (long long)n * TXT;
    const float* r  = R + row * D;
    float s = 0.f, s2 = 0.f;
    for (int i = threadIdx.x; i < D; i += 256) {
        float nd = (i < IMG) ? ig[i] : w[i - IMG];
        float v = nd + r[i];
        buf[i] = v;
        s += v; s2 += v * v;
    }
#pragma unroll
    for (int o = 16; o; o >>= 1) {
        s  += __shfl_down_sync(0xffffffffu, s, o);
        s2 += __shfl_down_sync(0xffffffffu, s2, o);
    }
    int lane = threadIdx.x & 31, wid = threadIdx.x >> 5;
    if (!lane) { w1s[wid] = s; w2s[wid] = s2; }
    __syncthreads();
    if (threadIdx.x == 0) {
        float a = 0.f, b2 = 0.f;
        for (int i = 0; i < 8; i++) { a += w1s[i]; b2 += w2s[i]; }
        w1s[0] = a; w2s[0] = b2;
    }
    __syncthreads();
    float mean = w1s[0] / D;
    float var  = w2s[0] / D - mean * mean;
    float inv  = rsqrtf(var + 1e-5f);
    float* o = out + row * D;
    __half* oh = outh + row * DP;
    for (int i = threadIdx.x; i < D; i += 256) {
        float v = (buf[i] - mean) * inv * g[i] + bb[i];
        o[i] = v;
        oh[i] = __float2half_rn(v);
    }
}

// ---------------- LN2: x2_h = fp16(LN(X + R)) ----------------
__global__ void ln_kernel(const float* __restrict__ X, const float* __restrict__ R,
                          const float* __restrict__ g, const float* __restrict__ bb,
                          __half* __restrict__ outh) {
    const int D = DD;
    long long row = blockIdx.x;
    __shared__ float buf[DD];
    __shared__ float w1s[8], w2s[8];
    const float* x = X + row * D;
    const float* r = R + row * D;
    float s = 0.f, s2 = 0.f;
    for (int i = threadIdx.x; i < D; i += 256) {
        float v = x[i] + r[i];
        buf[i] = v;
        s += v; s2 += v * v;
    }
#pragma unroll
    for (int o = 16; o; o >>= 1) {
        s  += __shfl_down_sync(0xffffffffu, s, o);
        s2 += __shfl_down_sync(0xffffffffu, s2, o);
    }
    int lane = threadIdx.x & 31, wid = threadIdx.x >> 5;
    if (!lane) { w1s[wid] = s; w2s[wid] = s2; }
    __syncthreads();
    if (threadIdx.x == 0) {
        float a = 0.f, b2 = 0.f;
        for (int i = 0; i < 8; i++) { a += w1s[i]; b2 += w2s[i]; }
        w1s[0] = a; w2s[0] = b2;
    }
    __syncthreads();
    float mean = w1s[0] / D;
    float var  = w2s[0] / D - mean * mean;
    float inv  = rsqrtf(var + 1e-5f);
    __half* oh = outh + row * DP;
    for (int i = threadIdx.x; i < D; i += 256)
        oh[i] = __float2half_rn((buf[i] - mean) * inv * g[i] + bb[i]);
}

// ---------------- GCN scatter-aggregate ----------------
__global__ void gcn_agg(const float* __restrict__ hin, const float* __restrict__ bias,
                        float* __restrict__ outf, __half* __restrict__ outh, int relu) {
    int b   = blockIdx.x / NN;
    int dst = blockIdx.x % NN;
    int h   = threadIdx.x;
    const float* base = hin + (long long)b * NN * HID;
    float acc = bias[h];
    int e0 = g_eoff[dst], e1 = g_eoff[dst + 1];
    for (int e = e0; e < e1; e++)
        acc += g_ewt[e] * base[g_esrc[e] * HID + h];
    if (relu) acc = fmaxf(acc, 0.f);
    long long idx = ((long long)b * NN + dst) * HID + h;
    if (outf) outf[idx] = acc;
    if (outh) outh[idx] = __float2half_rn(acc);
}

// ---------------- mean over nodes + relu ----------------
__global__ void pool_kernel(const float* __restrict__ g, float* __restrict__ out) {
    int idx = blockIdx.x * blockDim.x + threadIdx.x;
    if (idx >= BB * HID) return;
    int b = idx >> 7, h = idx & 127;
    const float* p = g + (long long)b * NN * HID + h;
    float s = 0.f;
#pragma unroll
    for (int n = 0; n < NN; n++) s += p[n * HID];
    s *= (1.f / (float)NN);
    out[idx] = fmaxf(s, 0.f);
}

// ---------------- launch ----------------
static inline int ceil_div(int a, int b) { return (a + b - 1) / b; }

extern "C" void kernel_launch(void* const* d_in, const int* in_sizes, int n_in,
                              void* d_out, int out_size) {
    const float* img   = (const float*)d_in[0];
    const float* we    = (const float*)d_in[1];
    const int*   ei    = (const int*)  d_in[2];
    const float* inw   = (const float*)d_in[3];
    const float* inb   = (const float*)d_in[4];
    const float* outw  = (const float*)d_in[5];
    const float* outb  = (const float*)d_in[6];
    const float* ln1g  = (const float*)d_in[7];
    const float* ln1b  = (const float*)d_in[8];
    const float* ln2g  = (const float*)d_in[9];
    const float* ln2b  = (const float*)d_in[10];
    const float* w1    = (const float*)d_in[11];
    const float* b1    = (const float*)d_in[12];
    const float* w2    = (const float*)d_in[13];
    const float* b2    = (const float*)d_in[14];
    const float* gw1   = (const float*)d_in[15];
    const float* gb1   = (const float*)d_in[16];
    const float* gw2   = (const float*)d_in[17];
    const float* gb2   = (const float*)d_in[18];
    const float* lw    = (const float*)d_in[19];
    const float* lb    = (const float*)d_in[20];
    float* out = (float*)d_out;

    float *qkvi, *qkvt, *S0, *Bq, *ovt, *ao2, *x1, *ff, *g1, *g3, *g4, *pool;
    __half *imgr_h, *inwr_h, *outwr_h, *qkvi_h, *VoT_h, *attn_h, *x1r_h;
    __half *w1t_h, *hid_h, *w2t_h, *x2_h, *gw1t_h, *g2_h, *gw2t_h;
    cudaGetSymbolAddress((void**)&qkvi, g_qkvi);
    cudaGetSymbolAddress((void**)&qkvt, g_qkvt);
    cudaGetSymbolAddress((void**)&S0,   g_S0);
    cudaGetSymbolAddress((void**)&Bq,   g_Bq);
    cudaGetSymbolAddress((void**)&ovt,  g_ovt);
    cudaGetSymbolAddress((void**)&ao2,  g_ao2);
    cudaGetSymbolAddress((void**)&x1,   g_x1);
    cudaGetSymbolAddress((void**)&ff,   g_ff);
    cudaGetSymbolAddress((void**)&g1,   g_g1);
    cudaGetSymbolAddress((void**)&g3,   g_g3);
    cudaGetSymbolAddress((void**)&g4,   g_g4);
    cudaGetSymbolAddress((void**)&pool, g_pool);
    cudaGetSymbolAddress((void**)&imgr_h,  g_imgr_h);
    cudaGetSymbolAddress((void**)&inwr_h,  g_inwr_h);
    cudaGetSymbolAddress((void**)&outwr_h, g_outwr_h);
    cudaGetSymbolAddress((void**)&qkvi_h,  g_qkvi_h);
    cudaGetSymbolAddress((void**)&VoT_h,   g_VoT_h);
    cudaGetSymbolAddress((void**)&attn_h,  g_attn_h);
    cudaGetSymbolAddress((void**)&x1r_h,   g_x1r_h);
    cudaGetSymbolAddress((void**)&w1t_h,   g_w1t_h);
    cudaGetSymbolAddress((void**)&hid_h,   g_hid_h);
    cudaGetSymbolAddress((void**)&w2t_h,   g_w2t_h);
    cudaGetSymbolAddress((void**)&x2_h,    g_x2_h);
    cudaGetSymbolAddress((void**)&gw1t_h,  g_gw1t_h);
    cudaGetSymbolAddress((void**)&g2_h,    g_g2_h);
    cudaGetSymbolAddress((void**)&gw2t_h,  g_gw2t_h);

    cudaFuncSetAttribute(hgemm<2>,
                         cudaFuncAttributeMaxDynamicSharedMemorySize, CAC<2>::SMEM);
    cudaFuncSetAttribute(hgemm<1>,
                         cudaFuncAttributeMaxDynamicSharedMemorySize, CAC<1>::SMEM);
    cudaFuncSetAttribute(hg_dual,
                         cudaFuncAttributeMaxDynamicSharedMemorySize, CAC<1>::SMEM);

    const float attn_scale = 1.0f / sqrtf((float)DD);

    // 0) PREP: fp16 converts + qkvt thin + edge_prep (one launch)
    {
        PrepArgs pa;
        pa.s[0] = { img,  imgr_h,  IMG, IMG, IMG, (long long)BB * IMG };
        pa.s[1] = { inw,  inwr_h,  DD,  IMG, IMG, (long long)D3 * IMG };
        pa.s[2] = { outw, outwr_h, DD,  DD,  DP,  (long long)DD * DD };
        int nblocks = 0;
        for (int k = 0; k < 3; k++) {
            pa.nb[k] = (int)((pa.s[k].total + 1023) / 1024);
            nblocks += pa.nb[k];
        }
        pa.we = we; pa.inw = inw; pa.inb = inb; pa.qkvt = qkvt; pa.ei = ei;
        nblocks += ceil_div(D3, 8) + 1;
        prep_kernel<<<nblocks, 256>>>(pa);
    }
    // 0b) transposed fp16 weights
    transpose_h<<<dim3(ceil_div(FF, 32), ceil_div(DD, 32)), dim3(32, 8)>>>(w1, w1t_h, DD, FF, DP);
    transpose_h<<<dim3(ceil_div(DD, 32), ceil_div(FF, 32)), dim3(32, 8)>>>(w2, w2t_h, FF, DD, FF);
    transpose_h<<<dim3(ceil_div(HID, 32), ceil_div(DD, 32)), dim3(32, 8)>>>(gw1, gw1t_h, DD, HID, DP);
    transpose_h<<<dim3(ceil_div(HID, 32), ceil_div(HID, 32)), dim3(32, 8)>>>(gw2, gw2t_h, HID, HID, HID);

    // 1) qkvi = img @ Win[:, :512]^T  -> fp32 qkvi + padded fp16 qkvi_h
    hgemm<2><<<dim3(ceil_div(D3, 128), 8, 1), 256, CAC<2>::SMEM>>>(
        BB, D3, IMG, imgr_h, IMG, 0, inwr_h, IMG, 0,
        qkvi, D3, 0, qkvi_h, QLD, 0, nullptr, 0, 0, 1);

    // 2) DUAL: S0 = qi@ki^T (fp32) || VoT = Wout@vi^T (fp16)
    {
        HG a0, a1;
        a0.A = qkvi_h; a0.lda = QLD; a0.B = qkvi_h + DP; a0.ldb = QLD;
        a0.C = S0; a0.ldc = BB; a0.Ch = nullptr; a0.ldh = 0;
        a0.M = BB; a0.N = BB; a0.K = DD;
        a1.A = outwr_h; a1.lda = DP; a1.B = qkvi_h + 2 * DP; a1.ldb = QLD;
        a1.C = nullptr; a1.ldc = 0; a1.Ch = VoT_h; a1.ldh = BB;
        a1.M = DD; a1.N = BB; a1.K = DD;
        hg_dual<<<dim3(8, 16, 2), 256, CAC<1>::SMEM>>>(a0, a1);
    }

    // 3) DUAL thin: Bq || ovt (fp32)
    {
        TPairArgs tp;
        tp.nb0 = ceil_div(BB, 8);
        tp.N0 = BB; tp.K0 = DD; tp.A0 = qkvt; tp.lda0 = D3;
        tp.B0 = qkvi + DD; tp.ldb0 = D3; tp.C0 = Bq; tp.ldc0 = BB; tp.bias0 = nullptr;
        tp.N1 = DD; tp.K1 = DD; tp.A1 = qkvt + 2 * DD; tp.lda1 = D3;
        tp.B1 = outw; tp.ldb1 = DD; tp.C1 = ovt; tp.ldc1 = DD; tp.bias1 = outb;
        thin_pair<<<tp.nb0 + ceil_div(DD, 8), 256>>>(tp);
    }

    // 4) attn_h = fp16(softmax(scale*(S0 + Bq)))
    softmax_fused<<<dim3(BB, NN), 256>>>(S0, Bq, attn_h, attn_scale);

    // 5) ao2[l,n,:] = attn_n @ VoT^T + ovt[n]  (fp32 out, batched over n)
    hgemm<2><<<dim3(ceil_div(DD, 128), 8, NN), 256, CAC<2>::SMEM>>>(
        BB, DD, BB,
        attn_h, BB, (long long)BB * BB,
        VoT_h, BB, 0,
        ao2, (long long)NN * DD, DD,
        nullptr, 0, 0,
        ovt, DD, 0, 0);

    // 6) x1 = LN(node + ao2); x1r_h fp16
    ln1_kernel<<<MM, 256>>>(img, we, ao2, ln1g, ln1b, x1, x1r_h);

    // 7) hid_h = fp16(relu(x1r @ w1^T + b1))
    hgemm<2><<<dim3(ceil_div(FF, 128), ceil_div(MM, 128), 1), 256, CAC<2>::SMEM>>>(
        MM, FF, DD, x1r_h, DP, 0, w1t_h, DP, 0,
        nullptr, 0, 0, hid_h, FF, 0, b1, 0, 1, 0);

    // 8) ff = hid @ w2^T + b2 (fp32)
    hgemm<2><<<dim3(ceil_div(DD, 128), ceil_div(MM, 128), 1), 256, CAC<2>::SMEM>>>(
        MM, DD, FF, hid_h, FF, 0, w2t_h, FF, 0,
        ff, DD, 0, nullptr, 0, 0, b2, 0, 0, 0);

    // 9) x2_h = fp16(LN(x1 + ff))
    ln_kernel<<<MM, 256>>>(x1, ff, ln2g, ln2b, x2_h);

    // 10) g1 = x2 @ gw1^T (fp32)
    hgemm<1><<<dim3(1, ceil_div(MM, 64), 1), 256, CAC<1>::SMEM>>>(
        MM, HID, DD, x2_h, DP, 0, gw1t_h, DP, 0,
        g1, HID, 0, nullptr, 0, 0, nullptr, 0, 0, 0);

    // 11) g2_h = fp16(relu(agg(g1) + gb1))
    gcn_agg<<<MM, HID>>>(g1, gb1, nullptr, g2_h, 1);

    // 12) g3 = g2 @ gw2^T (fp32)
    hgemm<1><<<dim3(1, ceil_div(MM, 64), 1), 256, CAC<1>::SMEM>>>(
        MM, HID, HID, g2_h, HID, 0, gw2t_h, HID, 0,
        g3, HID, 0, nullptr, 0, 0, nullptr, 0, 0, 0);

    // 13) g4 = agg(g3) + gb2 (fp32)
    gcn_agg<<<MM, HID>>>(g3, gb2, g4, nullptr, 0);

    // 14) pool = relu(mean over nodes)
    pool_kernel<<<(BB * HID + 255) / 256, 256>>>(g4, pool);

    // 15) out = pool @ lin_w + lin_b (fp32)
    sgemm_nt<<<dim3(1, ceil_div(BB, 128), 1), 256>>>(
        BB, CC, HID, pool, HID, lw, CC, out, CC, lb);
}